// round 1
// baseline (speedup 1.0000x reference)
#include <cuda_runtime.h>
#include <math.h>

// Problem dims (fixed by the dataset)
#define Hdim 4096
#define Ddim 1024
#define Adim 512
#define Bsz  4
#define LQd  2048
#define TMd  1500

#define QROWS (Bsz * LQd)   // 8192
#define MROWS (Bsz * TMd)   // 6000

// ---------------------------------------------------------------------------
// Scratch (static device arrays; allocation in kernel_launch is forbidden)
// ---------------------------------------------------------------------------
__device__ float g_hnorm[(size_t)QROWS * Hdim];   // 134 MB
__device__ float g_q    [(size_t)QROWS * Adim];   // 16.8 MB
__device__ float g_k    [(size_t)MROWS * Adim];   // 12.3 MB
__device__ float g_v    [(size_t)MROWS * Adim];   // 12.3 MB
__device__ float g_s    [(size_t)Bsz * LQd * TMd];// 49 MB
__device__ float g_ctx  [(size_t)QROWS * Adim];   // 16.8 MB
__device__ float g_ch   [(size_t)QROWS * Hdim];   // 134 MB

// ---------------------------------------------------------------------------
// Block reductions (256 threads)
// ---------------------------------------------------------------------------
__device__ __forceinline__ void block_sum2(float& s, float& ss) {
    #pragma unroll
    for (int o = 16; o > 0; o >>= 1) {
        s  += __shfl_xor_sync(0xffffffffu, s,  o);
        ss += __shfl_xor_sync(0xffffffffu, ss, o);
    }
    __shared__ float sh1[8], sh2[8];
    int wid = threadIdx.x >> 5;
    if ((threadIdx.x & 31) == 0) { sh1[wid] = s; sh2[wid] = ss; }
    __syncthreads();
    s = 0.f; ss = 0.f;
    #pragma unroll
    for (int i = 0; i < 8; i++) { s += sh1[i]; ss += sh2[i]; }
}

__device__ __forceinline__ float block_max256(float v) {
    #pragma unroll
    for (int o = 16; o > 0; o >>= 1)
        v = fmaxf(v, __shfl_xor_sync(0xffffffffu, v, o));
    __shared__ float shm[8];
    int wid = threadIdx.x >> 5;
    if ((threadIdx.x & 31) == 0) shm[wid] = v;
    __syncthreads();
    v = -3.4e38f;
    #pragma unroll
    for (int i = 0; i < 8; i++) v = fmaxf(v, shm[i]);
    return v;
}

__device__ __forceinline__ float block_sum256(float v) {
    #pragma unroll
    for (int o = 16; o > 0; o >>= 1)
        v += __shfl_xor_sync(0xffffffffu, v, o);
    __shared__ float shs[8];
    int wid = threadIdx.x >> 5;
    if ((threadIdx.x & 31) == 0) shs[wid] = v;
    __syncthreads();
    v = 0.f;
    #pragma unroll
    for (int i = 0; i < 8; i++) v += shs[i];
    return v;
}

// ---------------------------------------------------------------------------
// Input LayerNorm: one block per row of H=4096, 256 threads, 16 floats/thread
// ---------------------------------------------------------------------------
__global__ void ln_in_kernel(const float* __restrict__ x,
                             const float* __restrict__ w,
                             const float* __restrict__ b,
                             float* __restrict__ y) {
    const size_t row = blockIdx.x;
    const float4* xr = reinterpret_cast<const float4*>(x + row * Hdim);
    const float4* wr = reinterpret_cast<const float4*>(w);
    const float4* br = reinterpret_cast<const float4*>(b);
    float4* yr = reinterpret_cast<float4*>(y + row * Hdim);

    float4 v[4];
    float s = 0.f, ss = 0.f;
    #pragma unroll
    for (int i = 0; i < 4; i++) {
        v[i] = xr[threadIdx.x + i * 256];
        s  += v[i].x + v[i].y + v[i].z + v[i].w;
        ss += v[i].x * v[i].x + v[i].y * v[i].y + v[i].z * v[i].z + v[i].w * v[i].w;
    }
    block_sum2(s, ss);
    const float mu  = s * (1.f / Hdim);
    const float var = ss * (1.f / Hdim) - mu * mu;
    const float rs  = rsqrtf(var + 1e-5f);

    #pragma unroll
    for (int i = 0; i < 4; i++) {
        int idx = threadIdx.x + i * 256;
        float4 wv = wr[idx], bv = br[idx], o;
        o.x = (v[i].x - mu) * rs * wv.x + bv.x;
        o.y = (v[i].y - mu) * rs * wv.y + bv.y;
        o.z = (v[i].z - mu) * rs * wv.z + bv.z;
        o.w = (v[i].w - mu) * rs * wv.w + bv.w;
        yr[idx] = o;
    }
}

// ---------------------------------------------------------------------------
// Generic SIMT GEMM: C = alpha * A * op(B) + bias
//   A: [M,K] row-major.  TRANSB ? B: [N,K] row-major : B: [K,N] row-major.
//   128x128 block tile, BK=8, 256 threads, 8x8 per-thread microtile (4+4 split
//   to avoid LDS bank conflicts). All K,N are multiples of 4 in this problem,
//   so float4 loads never straddle a boundary; per-vector guards suffice.
// ---------------------------------------------------------------------------
template <bool TRANSB>
__global__ __launch_bounds__(256)
void gemm_kernel(const float* __restrict__ Ag, const float* __restrict__ Bg,
                 const float* __restrict__ bias, float* __restrict__ Cg,
                 int M, int N, int K, float alpha,
                 long sA, long sB, long sC) {
    const float* A = Ag + (long)blockIdx.z * sA;
    const float* B = Bg + (long)blockIdx.z * sB;
    float*       C = Cg + (long)blockIdx.z * sC;

    __shared__ float As[8][128];
    __shared__ float Bs[8][128];

    const int tid = threadIdx.x;
    const int tx = tid & 15;
    const int ty = tid >> 4;
    const int row0 = blockIdx.y * 128;
    const int col0 = blockIdx.x * 128;

    float acc[8][8];
    #pragma unroll
    for (int i = 0; i < 8; i++)
        #pragma unroll
        for (int j = 0; j < 8; j++) acc[i][j] = 0.f;

    const int a_m = tid >> 1;
    const int a_k = (tid & 1) * 4;

    for (int k0 = 0; k0 < K; k0 += 8) {
        // --- load A tile (transposed into As[k][m]) ---
        {
            float4 av = make_float4(0.f, 0.f, 0.f, 0.f);
            int gr = row0 + a_m, gk = k0 + a_k;
            if (gr < M && gk < K)
                av = *reinterpret_cast<const float4*>(A + (long)gr * K + gk);
            As[a_k    ][a_m] = av.x;
            As[a_k + 1][a_m] = av.y;
            As[a_k + 2][a_m] = av.z;
            As[a_k + 3][a_m] = av.w;
        }
        // --- load B tile into Bs[k][n] ---
        if (TRANSB) {
            int n_l = tid >> 1, k_l = (tid & 1) * 4;
            float4 bv = make_float4(0.f, 0.f, 0.f, 0.f);
            int gn = col0 + n_l, gk = k0 + k_l;
            if (gn < N && gk < K)
                bv = *reinterpret_cast<const float4*>(B + (long)gn * K + gk);
            Bs[k_l    ][n_l] = bv.x;
            Bs[k_l + 1][n_l] = bv.y;
            Bs[k_l + 2][n_l] = bv.z;
            Bs[k_l + 3][n_l] = bv.w;
        } else {
            int k_l = tid >> 5, n_l = (tid & 31) * 4;
            float4 bv = make_float4(0.f, 0.f, 0.f, 0.f);
            int gk = k0 + k_l, gn = col0 + n_l;
            if (gk < K && gn < N)
                bv = *reinterpret_cast<const float4*>(B + (long)gk * N + gn);
            *reinterpret_cast<float4*>(&Bs[k_l][n_l]) = bv;
        }
        __syncthreads();

        #pragma unroll
        for (int kk = 0; kk < 8; kk++) {
            float a[8], b[8];
            #pragma unroll
            for (int i = 0; i < 4; i++) {
                a[i]     = As[kk][ty * 4 + i];
                a[i + 4] = As[kk][64 + ty * 4 + i];
            }
            #pragma unroll
            for (int j = 0; j < 4; j++) {
                b[j]     = Bs[kk][tx * 4 + j];
                b[j + 4] = Bs[kk][64 + tx * 4 + j];
            }
            #pragma unroll
            for (int i = 0; i < 8; i++)
                #pragma unroll
                for (int j = 0; j < 8; j++)
                    acc[i][j] = fmaf(a[i], b[j], acc[i][j]);
        }
        __syncthreads();
    }

    // --- epilogue ---
    #pragma unroll
    for (int i = 0; i < 8; i++) {
        int r = row0 + ((i < 4) ? (ty * 4 + i) : (64 + ty * 4 + (i - 4)));
        if (r >= M) continue;
        #pragma unroll
        for (int jh = 0; jh < 2; jh++) {
            int c0 = col0 + ((jh == 0) ? (tx * 4) : (64 + tx * 4));
            if (c0 >= N) continue;
            float4 o;
            int jb = jh * 4;
            o.x = acc[i][jb + 0] * alpha;
            o.y = acc[i][jb + 1] * alpha;
            o.z = acc[i][jb + 2] * alpha;
            o.w = acc[i][jb + 3] * alpha;
            if (bias) {
                o.x += bias[c0 + 0]; o.y += bias[c0 + 1];
                o.z += bias[c0 + 2]; o.w += bias[c0 + 3];
            }
            *reinterpret_cast<float4*>(C + (long)r * N + c0) = o;
        }
    }
}

// ---------------------------------------------------------------------------
// Masked softmax over TM=1500; one block (256 thr) per (b, q) row, in place.
// ---------------------------------------------------------------------------
__global__ void softmax_kernel(float* __restrict__ S,
                               const unsigned char* __restrict__ mask) {
    const int b = blockIdx.x >> 11;                 // blockIdx.x / LQd
    float* row = S + (size_t)blockIdx.x * TMd;
    const unsigned char* mrow = mask + (size_t)b * TMd;

    float vals[6];
    float mx = -3.4e38f;
    #pragma unroll
    for (int i = 0; i < 6; i++) {
        int idx = threadIdx.x + i * 256;
        if (idx < TMd) {
            float v = row[idx];
            if (mrow[idx]) v = -1e30f;
            vals[i] = v;
            mx = fmaxf(mx, v);
        } else {
            vals[i] = -3.4e38f;
        }
    }
    mx = block_max256(mx);
    __syncthreads();

    float sum = 0.f;
    #pragma unroll
    for (int i = 0; i < 6; i++) {
        int idx = threadIdx.x + i * 256;
        if (idx < TMd) {
            float e = expf(vals[i] - mx);
            vals[i] = e;
            sum += e;
        }
    }
    sum = block_sum256(sum);
    const float inv = 1.f / sum;

    #pragma unroll
    for (int i = 0; i < 6; i++) {
        int idx = threadIdx.x + i * 256;
        if (idx < TMd) row[idx] = vals[i] * inv;
    }
}

// ---------------------------------------------------------------------------
// Fused epilogue: x = hidden + context_h ; out = hidden + g*(LN(x) - hidden)
// ---------------------------------------------------------------------------
__global__ void final_kernel(const float* __restrict__ h,
                             const float* __restrict__ ch,
                             const float* __restrict__ w,
                             const float* __restrict__ b,
                             const float* __restrict__ gate,
                             float* __restrict__ out) {
    const size_t row = blockIdx.x;
    const float4* hr = reinterpret_cast<const float4*>(h + row * Hdim);
    const float4* cr = reinterpret_cast<const float4*>(ch + row * Hdim);
    const float4* wr = reinterpret_cast<const float4*>(w);
    const float4* br = reinterpret_cast<const float4*>(b);
    float4* orow = reinterpret_cast<float4*>(out + row * Hdim);

    float4 hv[4], xv[4];
    float s = 0.f, ss = 0.f;
    #pragma unroll
    for (int i = 0; i < 4; i++) {
        hv[i] = hr[threadIdx.x + i * 256];
        float4 cv = cr[threadIdx.x + i * 256];
        xv[i].x = hv[i].x + cv.x;
        xv[i].y = hv[i].y + cv.y;
        xv[i].z = hv[i].z + cv.z;
        xv[i].w = hv[i].w + cv.w;
        s  += xv[i].x + xv[i].y + xv[i].z + xv[i].w;
        ss += xv[i].x * xv[i].x + xv[i].y * xv[i].y
            + xv[i].z * xv[i].z + xv[i].w * xv[i].w;
    }
    block_sum2(s, ss);
    const float mu  = s * (1.f / Hdim);
    const float var = ss * (1.f / Hdim) - mu * mu;
    const float rs  = rsqrtf(var + 1e-5f);
    const float g   = 1.f / (1.f + expf(-gate[0]));

    #pragma unroll
    for (int i = 0; i < 4; i++) {
        int idx = threadIdx.x + i * 256;
        float4 wv = wr[idx], bv = br[idx], o;
        float lnx;
        lnx = (xv[i].x - mu) * rs * wv.x + bv.x; o.x = hv[i].x + g * (lnx - hv[i].x);
        lnx = (xv[i].y - mu) * rs * wv.y + bv.y; o.y = hv[i].y + g * (lnx - hv[i].y);
        lnx = (xv[i].z - mu) * rs * wv.z + bv.z; o.z = hv[i].z + g * (lnx - hv[i].z);
        lnx = (xv[i].w - mu) * rs * wv.w + bv.w; o.w = hv[i].w + g * (lnx - hv[i].w);
        orow[idx] = o;
    }
}

// ---------------------------------------------------------------------------
// Launch
// ---------------------------------------------------------------------------
extern "C" void kernel_launch(void* const* d_in, const int* in_sizes, int n_in,
                              void* d_out, int out_size) {
    const float* hidden = (const float*)d_in[0];
    const float* mem    = (const float*)d_in[1];
    const unsigned char* mask = (const unsigned char*)d_in[2];
    const float* Wq = (const float*)d_in[3];
    const float* bq = (const float*)d_in[4];
    const float* Wk = (const float*)d_in[5];
    const float* bk = (const float*)d_in[6];
    const float* Wv = (const float*)d_in[7];
    const float* bv = (const float*)d_in[8];
    const float* Wo = (const float*)d_in[9];
    const float* bo = (const float*)d_in[10];
    const float* ln_in_w  = (const float*)d_in[11];
    const float* ln_in_b  = (const float*)d_in[12];
    const float* ln_out_w = (const float*)d_in[13];
    const float* ln_out_b = (const float*)d_in[14];
    const float* gate     = (const float*)d_in[15];
    float* out = (float*)d_out;

    float *p_hnorm, *p_q, *p_k, *p_v, *p_s, *p_ctx, *p_ch;
    cudaGetSymbolAddress((void**)&p_hnorm, g_hnorm);
    cudaGetSymbolAddress((void**)&p_q,     g_q);
    cudaGetSymbolAddress((void**)&p_k,     g_k);
    cudaGetSymbolAddress((void**)&p_v,     g_v);
    cudaGetSymbolAddress((void**)&p_s,     g_s);
    cudaGetSymbolAddress((void**)&p_ctx,   g_ctx);
    cudaGetSymbolAddress((void**)&p_ch,    g_ch);

    const float scale = 0.044194173824159216f;  // 1/sqrt(512)

    // 1. h_norm = LN(hidden)
    ln_in_kernel<<<QROWS, 256>>>(hidden, ln_in_w, ln_in_b, p_hnorm);

    // 2. Q = h_norm @ Wq + bq            [8192,512]  K=4096
    gemm_kernel<false><<<dim3(4, 64, 1), 256>>>(
        p_hnorm, Wq, bq, p_q, QROWS, Adim, Hdim, 1.f, 0, 0, 0);

    // 3. K = mem @ Wk + bk               [6000,512]  K=1024
    gemm_kernel<false><<<dim3(4, 47, 1), 256>>>(
        mem, Wk, bk, p_k, MROWS, Adim, Ddim, 1.f, 0, 0, 0);

    // 4. V = mem @ Wv + bv
    gemm_kernel<false><<<dim3(4, 47, 1), 256>>>(
        mem, Wv, bv, p_v, MROWS, Adim, Ddim, 1.f, 0, 0, 0);

    // 5. scores = scale * Q @ K^T        per-batch [2048,1500], K=512
    gemm_kernel<true><<<dim3(12, 16, Bsz), 256>>>(
        p_q, p_k, nullptr, p_s, LQd, TMd, Adim, scale,
        (long)LQd * Adim, (long)TMd * Adim, (long)LQd * TMd);

    // 6. softmax with mask (in place)
    softmax_kernel<<<QROWS, 256>>>(p_s, mask);

    // 7. context = P @ V                 per-batch [2048,512], K=1500
    gemm_kernel<false><<<dim3(4, 16, Bsz), 256>>>(
        p_s, p_v, nullptr, p_ctx, LQd, Adim, TMd, 1.f,
        (long)LQd * TMd, (long)TMd * Adim, (long)LQd * Adim);

    // 8. context_h = context @ Wo + bo   [8192,4096], K=512
    gemm_kernel<false><<<dim3(32, 64, 1), 256>>>(
        p_ctx, Wo, bo, p_ch, QROWS, Hdim, Adim, 1.f, 0, 0, 0);

    // 9. out = hidden + g*(LN(hidden + context_h) - hidden)
    final_kernel<<<QROWS, 256>>>(hidden, p_ch, ln_out_w, ln_out_b, gate, out);
}

// round 3
// speedup vs baseline: 3.4953x; 3.4953x over previous
#include <cuda_runtime.h>
#include <math.h>
#include <stdint.h>

// Problem dims
#define Hdim 4096
#define Ddim 1024
#define Adim 512
#define Bsz  4
#define LQd  2048
#define TMd  1500
#define TMp  1536

#define QROWS (Bsz * LQd)    // 8192

// ---------------------------------------------------------------------------
// Scratch
// ---------------------------------------------------------------------------
__device__ float g_hnorm[(size_t)QROWS * Hdim];
__device__ float g_memc [(size_t)Bsz * TMd * Ddim];
__device__ float g_q    [(size_t)QROWS * Adim];
__device__ float g_k    [(size_t)Bsz * TMp * Adim];
__device__ float g_v    [(size_t)Bsz * TMp * Adim];
__device__ float g_vt   [(size_t)Bsz * Adim * TMp];
__device__ float g_s    [(size_t)Bsz * LQd * TMp];
__device__ float g_ctx  [(size_t)QROWS * Adim];
__device__ float g_ch   [(size_t)QROWS * Hdim];
__device__ float g_wqt  [(size_t)Adim * Hdim];
__device__ float g_wkt  [(size_t)Adim * Ddim];
__device__ float g_wvt  [(size_t)Adim * Ddim];
__device__ float g_wot  [(size_t)Hdim * Adim];

// ---------------------------------------------------------------------------
// Helpers
// ---------------------------------------------------------------------------
__device__ __forceinline__ uint32_t smem_u32(const void* p) {
    uint32_t a;
    asm("{ .reg .u64 t; cvta.to.shared.u64 t, %1; cvt.u32.u64 %0, t; }" : "=r"(a) : "l"(p));
    return a;
}

__device__ __forceinline__ void cp_async16(void* dst, const void* src, int sz) {
    asm volatile("cp.async.cg.shared.global [%0], [%1], 16, %2;"
        :: "r"(smem_u32(dst)), "l"(src), "r"(sz) : "memory");
}
__device__ __forceinline__ void cp_commit() {
    asm volatile("cp.async.commit_group;" ::: "memory");
}
__device__ __forceinline__ void cp_wait2() {
    asm volatile("cp.async.wait_group 2;" ::: "memory");
}

__device__ __forceinline__ float tf32r(float x) {
    uint32_t u;
    asm("cvt.rna.tf32.f32 %0, %1;" : "=r"(u) : "f"(x));
    return __uint_as_float(u);
}

__device__ __forceinline__ void mma8(float* c, const uint32_t* a, const uint32_t* b) {
    asm volatile(
        "mma.sync.aligned.m16n8k8.row.col.f32.tf32.tf32.f32 "
        "{%0,%1,%2,%3}, {%4,%5,%6,%7}, {%8,%9}, {%0,%1,%2,%3};"
        : "+f"(c[0]), "+f"(c[1]), "+f"(c[2]), "+f"(c[3])
        : "r"(a[0]), "r"(a[1]), "r"(a[2]), "r"(a[3]), "r"(b[0]), "r"(b[1]));
}

// ---------------------------------------------------------------------------
// tf32 mma.sync GEMM:  C[M,N] = alpha * A[M,K] @ B[N,K]^T + bias
//   128x128x32 CTA tile, 8 warps (4x2), triple-buffered cp.async pipeline,
//   XOR-swizzled SMEM (conflict-free fragment loads).
//   Grid: (Npad/128, Mpad/128, batch). A rows >= Mvalid read as zero.
// ---------------------------------------------------------------------------
__global__ __launch_bounds__(256, 2)
void gemm_mma(const float* __restrict__ Ag, const float* __restrict__ Bg,
              const float* __restrict__ bias, float* __restrict__ Cg,
              int Mvalid, int K, int ldc, long sA, long sB, long sC,
              float alpha, int cvt_out)
{
    extern __shared__ float sm[];   // 3 stages * (4096 A + 4096 B) floats

    const int tid = threadIdx.x;
    const int wid = tid >> 5, lane = tid & 31;
    const int lq = lane >> 2, lm4 = lane & 3;
    const int wm = wid & 3, wn = wid >> 2;
    const int row0 = blockIdx.y * 128;
    const int col0 = blockIdx.x * 128;
    const float* A = Ag + (long)blockIdx.z * sA;
    const float* B = Bg + (long)blockIdx.z * sB;
    float*       C = Cg + (long)blockIdx.z * sC;
    const int NC = K >> 5;

    // per-lane swizzled column offsets: colOff[j] = 4*(j ^ lq) + lm4
    int colOff[8];
    #pragma unroll
    for (int j = 0; j < 8; j++) colOff[j] = 4 * (j ^ lq) + lm4;

    // loader indices: this thread handles 4 (r,g) pairs per tile
    int lr[4], lgo[4];
    #pragma unroll
    for (int i = 0; i < 4; i++) {
        int idx = tid + i * 256;
        lr[i] = idx >> 3;
        int g = idx & 7;
        lgo[i] = ((g ^ (lr[i] & 7)) << 2);    // swizzled float4 slot * 4
    }

    auto load_stage = [&](int s, int kc) {
        float* As = sm + s * 8192;
        float* Bs = As + 4096;
        #pragma unroll
        for (int i = 0; i < 4; i++) {
            int r = lr[i];
            int g4 = (tid + i * 256 & 7) * 4;
            int szA = (row0 + r < Mvalid) ? 16 : 0;
            cp_async16(As + r * 32 + lgo[i], A + (size_t)(row0 + r) * K + kc + g4, szA);
            cp_async16(Bs + r * 32 + lgo[i], B + (size_t)(col0 + r) * K + kc + g4, 16);
        }
    };

    float acc[2][8][4];
    #pragma unroll
    for (int mt = 0; mt < 2; mt++)
        #pragma unroll
        for (int nt = 0; nt < 8; nt++)
            #pragma unroll
            for (int e = 0; e < 4; e++) acc[mt][nt][e] = 0.f;

    // prologue: stages 0,1
    load_stage(0, 0); cp_commit();
    if (NC > 1) load_stage(1, 32);
    cp_commit();

    const int baseA0 = (wm * 32 + lq) * 32;          // mt=0 row base (floats)
    const int baseB0 = (wn * 64 + lq) * 32;

    for (int c = 0; c < NC; ++c) {
        int nc = c + 2;
        if (nc < NC) load_stage(nc % 3, nc * 32);
        cp_commit();
        cp_wait2();
        __syncthreads();

        const float* As = sm + (c % 3) * 8192;
        const float* Bs = As + 4096;

        #pragma unroll
        for (int kk = 0; kk < 4; ++kk) {
            uint32_t a[2][4], b[8][2];
            const int c0 = colOff[2 * kk], c1 = colOff[2 * kk + 1];
            #pragma unroll
            for (int mt = 0; mt < 2; mt++) {
                int ba = baseA0 + mt * 16 * 32;
                a[mt][0] = __float_as_uint(As[ba + c0]);
                a[mt][1] = __float_as_uint(As[ba + 256 + c0]);
                a[mt][2] = __float_as_uint(As[ba + c1]);
                a[mt][3] = __float_as_uint(As[ba + 256 + c1]);
            }
            #pragma unroll
            for (int nt = 0; nt < 8; nt++) {
                int bb = baseB0 + nt * 8 * 32;
                b[nt][0] = __float_as_uint(Bs[bb + c0]);
                b[nt][1] = __float_as_uint(Bs[bb + c1]);
            }
            #pragma unroll
            for (int mt = 0; mt < 2; mt++)
                #pragma unroll
                for (int nt = 0; nt < 8; nt++)
                    mma8(acc[mt][nt], a[mt], b[nt]);
        }
        __syncthreads();
    }

    // epilogue
    #pragma unroll
    for (int mt = 0; mt < 2; mt++) {
        int rg = row0 + wm * 32 + mt * 16 + lq;
        #pragma unroll
        for (int nt = 0; nt < 8; nt++) {
            int cg = col0 + wn * 64 + nt * 8 + 2 * lm4;
            float2 bv = make_float2(0.f, 0.f);
            if (bias) bv = __ldg(reinterpret_cast<const float2*>(bias + cg));
            float2 v0, v1;
            v0.x = acc[mt][nt][0] * alpha + bv.x;
            v0.y = acc[mt][nt][1] * alpha + bv.y;
            v1.x = acc[mt][nt][2] * alpha + bv.x;
            v1.y = acc[mt][nt][3] * alpha + bv.y;
            if (cvt_out) {
                v0.x = tf32r(v0.x); v0.y = tf32r(v0.y);
                v1.x = tf32r(v1.x); v1.y = tf32r(v1.y);
            }
            *reinterpret_cast<float2*>(C + (size_t)rg * ldc + cg) = v0;
            *reinterpret_cast<float2*>(C + (size_t)(rg + 8) * ldc + cg) = v1;
        }
    }
}

// ---------------------------------------------------------------------------
// Transpose with tf32 rounding: out[C,R] = tf32(in[R,C]^T)
// ---------------------------------------------------------------------------
__global__ void transpose_kernel(const float* __restrict__ in, float* __restrict__ out,
                                 int R, int C, long inB, long outB) {
    __shared__ float t[32][33];
    const float* ip = in + (long)blockIdx.z * inB;
    float* op = out + (long)blockIdx.z * outB;
    int r0 = blockIdx.y * 32, c0 = blockIdx.x * 32;
    int x = threadIdx.x, y = threadIdx.y;
    #pragma unroll
    for (int i = 0; i < 32; i += 8)
        t[y + i][x] = ip[(long)(r0 + y + i) * C + c0 + x];
    __syncthreads();
    #pragma unroll
    for (int i = 0; i < 32; i += 8)
        op[(long)(c0 + y + i) * R + r0 + x] = tf32r(t[x][y + i]);
}

// ---------------------------------------------------------------------------
// mem copy with tf32 rounding
// ---------------------------------------------------------------------------
__global__ void cvt_copy_kernel(const float4* __restrict__ in, float4* __restrict__ out, int n4) {
    int i = blockIdx.x * blockDim.x + threadIdx.x;
    if (i < n4) {
        float4 v = in[i];
        v.x = tf32r(v.x); v.y = tf32r(v.y); v.z = tf32r(v.z); v.w = tf32r(v.w);
        out[i] = v;
    }
}

// ---------------------------------------------------------------------------
// Block reductions (256 threads)
// ---------------------------------------------------------------------------
__device__ __forceinline__ void block_sum2(float& s, float& ss) {
    #pragma unroll
    for (int o = 16; o > 0; o >>= 1) {
        s  += __shfl_xor_sync(0xffffffffu, s,  o);
        ss += __shfl_xor_sync(0xffffffffu, ss, o);
    }
    __shared__ float sh1[8], sh2[8];
    int wid = threadIdx.x >> 5;
    if ((threadIdx.x & 31) == 0) { sh1[wid] = s; sh2[wid] = ss; }
    __syncthreads();
    s = 0.f; ss = 0.f;
    #pragma unroll
    for (int i = 0; i < 8; i++) { s += sh1[i]; ss += sh2[i]; }
}

__device__ __forceinline__ float block_max256(float v) {
    #pragma unroll
    for (int o = 16; o > 0; o >>= 1)
        v = fmaxf(v, __shfl_xor_sync(0xffffffffu, v, o));
    __shared__ float shm[8];
    int wid = threadIdx.x >> 5;
    if ((threadIdx.x & 31) == 0) shm[wid] = v;
    __syncthreads();
    v = -3.4e38f;
    #pragma unroll
    for (int i = 0; i < 8; i++) v = fmaxf(v, shm[i]);
    return v;
}

__device__ __forceinline__ float block_sum256(float v) {
    #pragma unroll
    for (int o = 16; o > 0; o >>= 1)
        v += __shfl_xor_sync(0xffffffffu, v, o);
    __shared__ float shs[8];
    int wid = threadIdx.x >> 5;
    if ((threadIdx.x & 31) == 0) shs[wid] = v;
    __syncthreads();
    v = 0.f;
    #pragma unroll
    for (int i = 0; i < 8; i++) v += shs[i];
    return v;
}

// ---------------------------------------------------------------------------
// Input LayerNorm (tf32-rounded output)
// ---------------------------------------------------------------------------
__global__ void ln_in_kernel(const float* __restrict__ x, const float* __restrict__ w,
                             const float* __restrict__ b, float* __restrict__ y) {
    const size_t row = blockIdx.x;
    const float4* xr = reinterpret_cast<const float4*>(x + row * Hdim);
    const float4* wr = reinterpret_cast<const float4*>(w);
    const float4* br = reinterpret_cast<const float4*>(b);
    float4* yr = reinterpret_cast<float4*>(y + row * Hdim);

    float4 v[4];
    float s = 0.f, ss = 0.f;
    #pragma unroll
    for (int i = 0; i < 4; i++) {
        v[i] = xr[threadIdx.x + i * 256];
        s  += v[i].x + v[i].y + v[i].z + v[i].w;
        ss += v[i].x * v[i].x + v[i].y * v[i].y + v[i].z * v[i].z + v[i].w * v[i].w;
    }
    block_sum2(s, ss);
    const float mu  = s * (1.f / Hdim);
    const float var = ss * (1.f / Hdim) - mu * mu;
    const float rs  = rsqrtf(var + 1e-5f);
    #pragma unroll
    for (int i = 0; i < 4; i++) {
        int idx = threadIdx.x + i * 256;
        float4 wv = wr[idx], bv = br[idx], o;
        o.x = tf32r((v[i].x - mu) * rs * wv.x + bv.x);
        o.y = tf32r((v[i].y - mu) * rs * wv.y + bv.y);
        o.z = tf32r((v[i].z - mu) * rs * wv.z + bv.z);
        o.w = tf32r((v[i].w - mu) * rs * wv.w + bv.w);
        yr[idx] = o;
    }
}

// ---------------------------------------------------------------------------
// Masked softmax, row stride TMp; tf32-rounded probs; zero pad cols
// ---------------------------------------------------------------------------
__global__ void softmax_kernel(float* __restrict__ S, const unsigned char* __restrict__ mask) {
    const int b = blockIdx.x >> 11;
    float* row = S + (size_t)blockIdx.x * TMp;
    const unsigned char* mrow = mask + (size_t)b * TMd;

    float vals[6];
    float mx = -3.4e38f;
    #pragma unroll
    for (int i = 0; i < 6; i++) {
        int idx = threadIdx.x + i * 256;
        if (idx < TMd) {
            float v = row[idx];
            if (mrow[idx]) v = -1e30f;
            vals[i] = v;
            mx = fmaxf(mx, v);
        } else vals[i] = -3.4e38f;
    }
    mx = block_max256(mx);
    __syncthreads();

    float sum = 0.f;
    #pragma unroll
    for (int i = 0; i < 6; i++) {
        int idx = threadIdx.x + i * 256;
        if (idx < TMd) {
            float e = expf(vals[i] - mx);
            vals[i] = e;
            sum += e;
        }
    }
    sum = block_sum256(sum);
    const float inv = 1.f / sum;

    #pragma unroll
    for (int i = 0; i < 6; i++) {
        int idx = threadIdx.x + i * 256;
        if (idx < TMd) row[idx] = tf32r(vals[i] * inv);
        else if (idx < TMp) row[idx] = 0.f;
    }
}

// ---------------------------------------------------------------------------
// Fused epilogue
// ---------------------------------------------------------------------------
__global__ void final_kernel(const float* __restrict__ h, const float* __restrict__ ch,
                             const float* __restrict__ w, const float* __restrict__ b,
                             const float* __restrict__ gate, float* __restrict__ out) {
    const size_t row = blockIdx.x;
    const float4* hr = reinterpret_cast<const float4*>(h + row * Hdim);
    const float4* cr = reinterpret_cast<const float4*>(ch + row * Hdim);
    const float4* wr = reinterpret_cast<const float4*>(w);
    const float4* br = reinterpret_cast<const float4*>(b);
    float4* orow = reinterpret_cast<float4*>(out + row * Hdim);

    float4 hv[4], xv[4];
    float s = 0.f, ss = 0.f;
    #pragma unroll
    for (int i = 0; i < 4; i++) {
        hv[i] = hr[threadIdx.x + i * 256];
        float4 cv = cr[threadIdx.x + i * 256];
        xv[i].x = hv[i].x + cv.x;
        xv[i].y = hv[i].y + cv.y;
        xv[i].z = hv[i].z + cv.z;
        xv[i].w = hv[i].w + cv.w;
        s  += xv[i].x + xv[i].y + xv[i].z + xv[i].w;
        ss += xv[i].x * xv[i].x + xv[i].y * xv[i].y + xv[i].z * xv[i].z + xv[i].w * xv[i].w;
    }
    block_sum2(s, ss);
    const float mu  = s * (1.f / Hdim);
    const float var = ss * (1.f / Hdim) - mu * mu;
    const float rs  = rsqrtf(var + 1e-5f);
    const float g   = 1.f / (1.f + expf(-gate[0]));

    #pragma unroll
    for (int i = 0; i < 4; i++) {
        int idx = threadIdx.x + i * 256;
        float4 wv = wr[idx], bv = br[idx], o;
        float lnx;
        lnx = (xv[i].x - mu) * rs * wv.x + bv.x; o.x = hv[i].x + g * (lnx - hv[i].x);
        lnx = (xv[i].y - mu) * rs * wv.y + bv.y; o.y = hv[i].y + g * (lnx - hv[i].y);
        lnx = (xv[i].z - mu) * rs * wv.z + bv.z; o.z = hv[i].z + g * (lnx - hv[i].z);
        lnx = (xv[i].w - mu) * rs * wv.w + bv.w; o.w = hv[i].w + g * (lnx - hv[i].w);
        orow[idx] = o;
    }
}

// ---------------------------------------------------------------------------
// Launch
// ---------------------------------------------------------------------------
extern "C" void kernel_launch(void* const* d_in, const int* in_sizes, int n_in,
                              void* d_out, int out_size) {
    const float* hidden = (const float*)d_in[0];
    const float* mem    = (const float*)d_in[1];
    const unsigned char* mask = (const unsigned char*)d_in[2];
    const float* Wq = (const float*)d_in[3];
    const float* bq = (const float*)d_in[4];
    const float* Wk = (const float*)d_in[5];
    const float* bk = (const float*)d_in[6];
    const float* Wv = (const float*)d_in[7];
    const float* bv = (const float*)d_in[8];
    const float* Wo = (const float*)d_in[9];
    const float* bo = (const float*)d_in[10];
    const float* ln_in_w  = (const float*)d_in[11];
    const float* ln_in_b  = (const float*)d_in[12];
    const float* ln_out_w = (const float*)d_in[13];
    const float* ln_out_b = (const float*)d_in[14];
    const float* gate     = (const float*)d_in[15];
    float* out = (float*)d_out;

    float *p_hnorm, *p_memc, *p_q, *p_k, *p_v, *p_vt, *p_s, *p_ctx, *p_ch;
    float *p_wqt, *p_wkt, *p_wvt, *p_wot;
    cudaGetSymbolAddress((void**)&p_hnorm, g_hnorm);
    cudaGetSymbolAddress((void**)&p_memc, g_memc);
    cudaGetSymbolAddress((void**)&p_q,   g_q);
    cudaGetSymbolAddress((void**)&p_k,   g_k);
    cudaGetSymbolAddress((void**)&p_v,   g_v);
    cudaGetSymbolAddress((void**)&p_vt,  g_vt);
    cudaGetSymbolAddress((void**)&p_s,   g_s);
    cudaGetSymbolAddress((void**)&p_ctx, g_ctx);
    cudaGetSymbolAddress((void**)&p_ch,  g_ch);
    cudaGetSymbolAddress((void**)&p_wqt, g_wqt);
    cudaGetSymbolAddress((void**)&p_wkt, g_wkt);
    cudaGetSymbolAddress((void**)&p_wvt, g_wvt);
    cudaGetSymbolAddress((void**)&p_wot, g_wot);

    const int SMEM_GEMM = 3 * 8192 * 4;   // 98304 B
    cudaFuncSetAttribute(gemm_mma, cudaFuncAttributeMaxDynamicSharedMemorySize, SMEM_GEMM);

    const float scale = 0.044194173824159216f;  // 1/sqrt(512)

    // producers (tf32-rounded outputs)
    ln_in_kernel<<<QROWS, 256>>>(hidden, ln_in_w, ln_in_b, p_hnorm);
    cvt_copy_kernel<<<(Bsz * TMd * Ddim / 4 + 255) / 256, 256>>>(
        (const float4*)mem, (float4*)p_memc, Bsz * TMd * Ddim / 4);
    transpose_kernel<<<dim3(16, 128, 1), dim3(32, 8)>>>(Wq, p_wqt, Hdim, Adim, 0, 0);
    transpose_kernel<<<dim3(16, 32, 1),  dim3(32, 8)>>>(Wk, p_wkt, Ddim, Adim, 0, 0);
    transpose_kernel<<<dim3(16, 32, 1),  dim3(32, 8)>>>(Wv, p_wvt, Ddim, Adim, 0, 0);
    transpose_kernel<<<dim3(128, 16, 1), dim3(32, 8)>>>(Wo, p_wot, Adim, Hdim, 0, 0);

    // Q = hnorm @ Wq + bq                [8192,512]  K=4096
    gemm_mma<<<dim3(4, 64, 1), 256, SMEM_GEMM>>>(
        p_hnorm, p_wqt, bq, p_q, QROWS, Hdim, Adim, 0, 0, 0, 1.f, 1);

    // K = mem @ Wk + bk   (per batch, M=1500 padded to 1536)
    gemm_mma<<<dim3(4, 12, Bsz), 256, SMEM_GEMM>>>(
        p_memc, p_wkt, bk, p_k, TMd, Ddim, Adim,
        (long)TMd * Ddim, 0, (long)TMp * Adim, 1.f, 1);

    // V = mem @ Wv + bv
    gemm_mma<<<dim3(4, 12, Bsz), 256, SMEM_GEMM>>>(
        p_memc, p_wvt, bv, p_v, TMd, Ddim, Adim,
        (long)TMd * Ddim, 0, (long)TMp * Adim, 1.f, 0);

    // V^T per batch: [1536,512] -> [512,1536]  (tf32-rounded)
    transpose_kernel<<<dim3(16, 48, Bsz), dim3(32, 8)>>>(
        p_v, p_vt, TMp, Adim, (long)TMp * Adim, (long)Adim * TMp);

    // scores = scale * Q @ K^T           per batch [2048,1536]  K=512
    gemm_mma<<<dim3(12, 16, Bsz), 256, SMEM_GEMM>>>(
        p_q, p_k, nullptr, p_s, LQd, Adim, TMp,
        (long)LQd * Adim, (long)TMp * Adim, (long)LQd * TMp, scale, 0);

    // softmax (masked, tf32-rounded probs, zero pad cols)
    softmax_kernel<<<QROWS, 256>>>(p_s, mask);

    // context = P @ (V^T)^T              per batch [2048,512]  K=1536
    gemm_mma<<<dim3(4, 16, Bsz), 256, SMEM_GEMM>>>(
        p_s, p_vt, nullptr, p_ctx, LQd, TMp, Adim,
        (long)LQd * TMp, (long)Adim * TMp, (long)LQd * Adim, 1.f, 1);

    // context_h = context @ Wo + bo      [8192,4096]  K=512
    gemm_mma<<<dim3(32, 64, 1), 256, SMEM_GEMM>>>(
        p_ctx, p_wot, bo, p_ch, QROWS, Adim, Hdim, 0, 0, 0, 1.f, 0);

    // out
    final_kernel<<<QROWS, 256>>>(hidden, p_ch, ln_out_w, ln_out_b, gate, out);
}

// round 4
// speedup vs baseline: 5.9816x; 1.7113x over previous
#include <cuda_runtime.h>
#include <cuda_bf16.h>
#include <math.h>
#include <stdint.h>

// Problem dims
#define Hdim 4096
#define Ddim 1024
#define Adim 512
#define Bsz  4
#define LQd  2048
#define TMd  1500
#define TMp  1536

#define QROWS (Bsz * LQd)    // 8192

// ---------------------------------------------------------------------------
// Scratch
// ---------------------------------------------------------------------------
__device__ __nv_bfloat16 g_hnorm[(size_t)QROWS * Hdim];
__device__ __nv_bfloat16 g_memc [(size_t)Bsz * TMd * Ddim];
__device__ __nv_bfloat16 g_q    [(size_t)QROWS * Adim];
__device__ __nv_bfloat16 g_k    [(size_t)Bsz * TMp * Adim];
__device__ float         g_v    [(size_t)Bsz * TMp * Adim];
__device__ __nv_bfloat16 g_vt   [(size_t)Bsz * Adim * TMp];
__device__ float         g_s    [(size_t)Bsz * LQd * TMp];
__device__ __nv_bfloat16 g_pb   [(size_t)Bsz * LQd * TMp];
__device__ __nv_bfloat16 g_ctx  [(size_t)QROWS * Adim];
__device__ float         g_ch   [(size_t)QROWS * Hdim];
__device__ __nv_bfloat16 g_wqt  [(size_t)Adim * Hdim];
__device__ __nv_bfloat16 g_wkt  [(size_t)Adim * Ddim];
__device__ __nv_bfloat16 g_wvt  [(size_t)Adim * Ddim];
__device__ __nv_bfloat16 g_wot  [(size_t)Hdim * Adim];

// ---------------------------------------------------------------------------
// Helpers
// ---------------------------------------------------------------------------
__device__ __forceinline__ uint32_t smem_u32(const void* p) {
    uint32_t a;
    asm("{ .reg .u64 t; cvta.to.shared.u64 t, %1; cvt.u32.u64 %0, t; }" : "=r"(a) : "l"(p));
    return a;
}

__device__ __forceinline__ void cp_async16(void* dst, const void* src, int sz) {
    asm volatile("cp.async.cg.shared.global [%0], [%1], 16, %2;"
        :: "r"(smem_u32(dst)), "l"(src), "r"(sz) : "memory");
}
__device__ __forceinline__ void cp_commit() {
    asm volatile("cp.async.commit_group;" ::: "memory");
}
__device__ __forceinline__ void cp_wait2() {
    asm volatile("cp.async.wait_group 2;" ::: "memory");
}

__device__ __forceinline__ void mma_bf16(float* c, const uint32_t* a, const uint32_t* b) {
    asm volatile(
        "mma.sync.aligned.m16n8k16.row.col.f32.bf16.bf16.f32 "
        "{%0,%1,%2,%3}, {%4,%5,%6,%7}, {%8,%9}, {%0,%1,%2,%3};"
        : "+f"(c[0]), "+f"(c[1]), "+f"(c[2]), "+f"(c[3])
        : "r"(a[0]), "r"(a[1]), "r"(a[2]), "r"(a[3]), "r"(b[0]), "r"(b[1]));
}

// ---------------------------------------------------------------------------
// bf16 mma.sync GEMM:  C[M,N] = alpha * A[M,K] @ B[N,K]^T + bias
//   128x128x64 CTA tile, 8 warps (4x2), triple-buffered cp.async pipeline,
//   16B-granule XOR swizzle (conflict-free fragment LDS.32).
//   A rows >= Mvalid read as zero (cp.async src-size 0).
// ---------------------------------------------------------------------------
#define STAGE_BYTES 32768     // 16KB A + 16KB B (128 rows x 128B each)

__global__ __launch_bounds__(256, 2)
void gemm_mma(const __nv_bfloat16* __restrict__ Ag, const __nv_bfloat16* __restrict__ Bg,
              const float* __restrict__ bias, void* __restrict__ Cg,
              int Mvalid, int K, int ldc, long sA, long sB, long sC,
              float alpha, int outBF16)
{
    extern __shared__ char sm[];   // 3 * STAGE_BYTES

    const int tid = threadIdx.x;
    const int wid = tid >> 5, lane = tid & 31;
    const int lq = lane >> 2, lm4 = lane & 3;
    const int wm = wid & 3, wn = wid >> 2;
    const int row0 = blockIdx.y * 128;
    const int col0 = blockIdx.x * 128;
    const __nv_bfloat16* A = Ag + (long)blockIdx.z * sA;
    const __nv_bfloat16* B = Bg + (long)blockIdx.z * sB;
    const int NC = K >> 6;         // 64 elements per chunk

    // loader: 4 (row, granule) pairs per matrix per thread
    auto load_stage = [&](int s, int kc) {
        char* As = sm + s * STAGE_BYTES;
        char* Bs = As + 16384;
        #pragma unroll
        for (int i = 0; i < 4; i++) {
            int idx = tid + i * 256;            // 0..1023
            int r = idx >> 3, g = idx & 7;
            int dst = r * 128 + ((g ^ (r & 7)) << 4);
            int szA = (row0 + r < Mvalid) ? 16 : 0;
            cp_async16(As + dst, A + (size_t)(row0 + r) * K + kc + g * 8, szA);
            cp_async16(Bs + dst, B + (size_t)(col0 + r) * K + kc + g * 8, 16);
        }
    };

    float acc[2][8][4];
    #pragma unroll
    for (int mt = 0; mt < 2; mt++)
        #pragma unroll
        for (int nt = 0; nt < 8; nt++)
            #pragma unroll
            for (int e = 0; e < 4; e++) acc[mt][nt][e] = 0.f;

    load_stage(0, 0); cp_commit();
    if (NC > 1) load_stage(1, 64);
    cp_commit();

    const int rA0 = wm * 32 + lq;     // A fragment base row
    const int rB0 = wn * 64 + lq;     // B fragment base row

    for (int c = 0; c < NC; ++c) {
        int nc = c + 2;
        if (nc < NC) load_stage(nc % 3, nc * 64);
        cp_commit();
        cp_wait2();
        __syncthreads();

        const uint32_t* As32 = reinterpret_cast<const uint32_t*>(sm + (c % 3) * STAGE_BYTES);
        const uint32_t* Bs32 = As32 + 4096;

        #pragma unroll
        for (int ks = 0; ks < 4; ++ks) {
            const int g0 = (((2 * ks)     ^ lq) << 2) + lm4;
            const int g1 = (((2 * ks + 1) ^ lq) << 2) + lm4;
            uint32_t a[2][4], b[8][2];
            #pragma unroll
            for (int mt = 0; mt < 2; mt++) {
                int r = rA0 + mt * 16;
                a[mt][0] = As32[r * 32 + g0];
                a[mt][1] = As32[(r + 8) * 32 + g0];
                a[mt][2] = As32[r * 32 + g1];
                a[mt][3] = As32[(r + 8) * 32 + g1];
            }
            #pragma unroll
            for (int nt = 0; nt < 8; nt++) {
                int r = rB0 + nt * 8;
                b[nt][0] = Bs32[r * 32 + g0];
                b[nt][1] = Bs32[r * 32 + g1];
            }
            #pragma unroll
            for (int mt = 0; mt < 2; mt++)
                #pragma unroll
                for (int nt = 0; nt < 8; nt++)
                    mma_bf16(acc[mt][nt], a[mt], b[nt]);
        }
        __syncthreads();
    }

    // epilogue
    #pragma unroll
    for (int mt = 0; mt < 2; mt++) {
        int rg = row0 + wm * 32 + mt * 16 + lq;
        #pragma unroll
        for (int nt = 0; nt < 8; nt++) {
            int cg = col0 + wn * 64 + nt * 8 + 2 * lm4;
            float2 bv = make_float2(0.f, 0.f);
            if (bias) bv = __ldg(reinterpret_cast<const float2*>(bias + cg));
            float2 v0, v1;
            v0.x = acc[mt][nt][0] * alpha + bv.x;
            v0.y = acc[mt][nt][1] * alpha + bv.y;
            v1.x = acc[mt][nt][2] * alpha + bv.x;
            v1.y = acc[mt][nt][3] * alpha + bv.y;
            if (outBF16) {
                __nv_bfloat16* C = (__nv_bfloat16*)Cg + (long)blockIdx.z * sC;
                *reinterpret_cast<__nv_bfloat162*>(C + (size_t)rg * ldc + cg) =
                    __floats2bfloat162_rn(v0.x, v0.y);
                *reinterpret_cast<__nv_bfloat162*>(C + (size_t)(rg + 8) * ldc + cg) =
                    __floats2bfloat162_rn(v1.x, v1.y);
            } else {
                float* C = (float*)Cg + (long)blockIdx.z * sC;
                *reinterpret_cast<float2*>(C + (size_t)rg * ldc + cg) = v0;
                *reinterpret_cast<float2*>(C + (size_t)(rg + 8) * ldc + cg) = v1;
            }
        }
    }
}

// ---------------------------------------------------------------------------
// Transpose: out[C,R] = bf16(in[R,C]^T)
// ---------------------------------------------------------------------------
__global__ void transpose_kernel(const float* __restrict__ in, __nv_bfloat16* __restrict__ out,
                                 int R, int C, long inB, long outB) {
    __shared__ float t[32][33];
    const float* ip = in + (long)blockIdx.z * inB;
    __nv_bfloat16* op = out + (long)blockIdx.z * outB;
    int r0 = blockIdx.y * 32, c0 = blockIdx.x * 32;
    int x = threadIdx.x, y = threadIdx.y;
    #pragma unroll
    for (int i = 0; i < 32; i += 8)
        t[y + i][x] = ip[(long)(r0 + y + i) * C + c0 + x];
    __syncthreads();
    #pragma unroll
    for (int i = 0; i < 32; i += 8)
        op[(long)(c0 + y + i) * R + r0 + x] = __float2bfloat16(t[x][y + i]);
}

// ---------------------------------------------------------------------------
// fp32 -> bf16 copy
// ---------------------------------------------------------------------------
__global__ void cvt_copy_kernel(const float4* __restrict__ in,
                                __nv_bfloat162* __restrict__ out, int n4) {
    int i = blockIdx.x * blockDim.x + threadIdx.x;
    if (i < n4) {
        float4 v = in[i];
        out[2 * i]     = __floats2bfloat162_rn(v.x, v.y);
        out[2 * i + 1] = __floats2bfloat162_rn(v.z, v.w);
    }
}

// ---------------------------------------------------------------------------
// Block reductions (256 threads)
// ---------------------------------------------------------------------------
__device__ __forceinline__ void block_sum2(float& s, float& ss) {
    #pragma unroll
    for (int o = 16; o > 0; o >>= 1) {
        s  += __shfl_xor_sync(0xffffffffu, s,  o);
        ss += __shfl_xor_sync(0xffffffffu, ss, o);
    }
    __shared__ float sh1[8], sh2[8];
    int wid = threadIdx.x >> 5;
    if ((threadIdx.x & 31) == 0) { sh1[wid] = s; sh2[wid] = ss; }
    __syncthreads();
    s = 0.f; ss = 0.f;
    #pragma unroll
    for (int i = 0; i < 8; i++) { s += sh1[i]; ss += sh2[i]; }
}

__device__ __forceinline__ float block_max256(float v) {
    #pragma unroll
    for (int o = 16; o > 0; o >>= 1)
        v = fmaxf(v, __shfl_xor_sync(0xffffffffu, v, o));
    __shared__ float shm[8];
    int wid = threadIdx.x >> 5;
    if ((threadIdx.x & 31) == 0) shm[wid] = v;
    __syncthreads();
    v = -3.4e38f;
    #pragma unroll
    for (int i = 0; i < 8; i++) v = fmaxf(v, shm[i]);
    return v;
}

__device__ __forceinline__ float block_sum256(float v) {
    #pragma unroll
    for (int o = 16; o > 0; o >>= 1)
        v += __shfl_xor_sync(0xffffffffu, v, o);
    __shared__ float shs[8];
    int wid = threadIdx.x >> 5;
    if ((threadIdx.x & 31) == 0) shs[wid] = v;
    __syncthreads();
    v = 0.f;
    #pragma unroll
    for (int i = 0; i < 8; i++) v += shs[i];
    return v;
}

// ---------------------------------------------------------------------------
// Input LayerNorm (bf16 output)
// ---------------------------------------------------------------------------
__global__ void ln_in_kernel(const float* __restrict__ x, const float* __restrict__ w,
                             const float* __restrict__ b, __nv_bfloat16* __restrict__ y) {
    const size_t row = blockIdx.x;
    const float4* xr = reinterpret_cast<const float4*>(x + row * Hdim);
    const float4* wr = reinterpret_cast<const float4*>(w);
    const float4* br = reinterpret_cast<const float4*>(b);
    __nv_bfloat162* yr = reinterpret_cast<__nv_bfloat162*>(y + row * Hdim);

    float4 v[4];
    float s = 0.f, ss = 0.f;
    #pragma unroll
    for (int i = 0; i < 4; i++) {
        v[i] = xr[threadIdx.x + i * 256];
        s  += v[i].x + v[i].y + v[i].z + v[i].w;
        ss += v[i].x * v[i].x + v[i].y * v[i].y + v[i].z * v[i].z + v[i].w * v[i].w;
    }
    block_sum2(s, ss);
    const float mu  = s * (1.f / Hdim);
    const float var = ss * (1.f / Hdim) - mu * mu;
    const float rs  = rsqrtf(var + 1e-5f);
    #pragma unroll
    for (int i = 0; i < 4; i++) {
        int idx = threadIdx.x + i * 256;
        float4 wv = wr[idx], bv = br[idx];
        float ox = (v[i].x - mu) * rs * wv.x + bv.x;
        float oy = (v[i].y - mu) * rs * wv.y + bv.y;
        float oz = (v[i].z - mu) * rs * wv.z + bv.z;
        float ow = (v[i].w - mu) * rs * wv.w + bv.w;
        yr[2 * idx]     = __floats2bfloat162_rn(ox, oy);
        yr[2 * idx + 1] = __floats2bfloat162_rn(oz, ow);
    }
}

// ---------------------------------------------------------------------------
// Masked softmax: read fp32 scores (stride TMp), write bf16 probs (stride TMp)
// ---------------------------------------------------------------------------
__global__ void softmax_kernel(const float* __restrict__ S, const unsigned char* __restrict__ mask,
                               __nv_bfloat16* __restrict__ P) {
    const int b = blockIdx.x >> 11;
    const float* row = S + (size_t)blockIdx.x * TMp;
    __nv_bfloat16* prow = P + (size_t)blockIdx.x * TMp;
    const unsigned char* mrow = mask + (size_t)b * TMd;

    float vals[6];
    float mx = -3.4e38f;
    #pragma unroll
    for (int i = 0; i < 6; i++) {
        int idx = threadIdx.x + i * 256;
        if (idx < TMd) {
            float v = row[idx];
            if (mrow[idx]) v = -1e30f;
            vals[i] = v;
            mx = fmaxf(mx, v);
        } else vals[i] = -3.4e38f;
    }
    mx = block_max256(mx);
    __syncthreads();

    float sum = 0.f;
    #pragma unroll
    for (int i = 0; i < 6; i++) {
        int idx = threadIdx.x + i * 256;
        if (idx < TMd) {
            float e = __expf(vals[i] - mx);
            vals[i] = e;
            sum += e;
        }
    }
    sum = block_sum256(sum);
    const float inv = 1.f / sum;

    #pragma unroll
    for (int i = 0; i < 6; i++) {
        int idx = threadIdx.x + i * 256;
        if (idx < TMd) prow[idx] = __float2bfloat16(vals[i] * inv);
        else if (idx < TMp) prow[idx] = __float2bfloat16(0.f);
    }
}

// ---------------------------------------------------------------------------
// Fused epilogue
// ---------------------------------------------------------------------------
__global__ void final_kernel(const float* __restrict__ h, const float* __restrict__ ch,
                             const float* __restrict__ w, const float* __restrict__ b,
                             const float* __restrict__ gate, float* __restrict__ out) {
    const size_t row = blockIdx.x;
    const float4* hr = reinterpret_cast<const float4*>(h + row * Hdim);
    const float4* cr = reinterpret_cast<const float4*>(ch + row * Hdim);
    const float4* wr = reinterpret_cast<const float4*>(w);
    const float4* br = reinterpret_cast<const float4*>(b);
    float4* orow = reinterpret_cast<float4*>(out + row * Hdim);

    float4 hv[4], xv[4];
    float s = 0.f, ss = 0.f;
    #pragma unroll
    for (int i = 0; i < 4; i++) {
        hv[i] = hr[threadIdx.x + i * 256];
        float4 cv = cr[threadIdx.x + i * 256];
        xv[i].x = hv[i].x + cv.x;
        xv[i].y = hv[i].y + cv.y;
        xv[i].z = hv[i].z + cv.z;
        xv[i].w = hv[i].w + cv.w;
        s  += xv[i].x + xv[i].y + xv[i].z + xv[i].w;
        ss += xv[i].x * xv[i].x + xv[i].y * xv[i].y + xv[i].z * xv[i].z + xv[i].w * xv[i].w;
    }
    block_sum2(s, ss);
    const float mu  = s * (1.f / Hdim);
    const float var = ss * (1.f / Hdim) - mu * mu;
    const float rs  = rsqrtf(var + 1e-5f);
    const float g   = 1.f / (1.f + expf(-gate[0]));

    #pragma unroll
    for (int i = 0; i < 4; i++) {
        int idx = threadIdx.x + i * 256;
        float4 wv = wr[idx], bv = br[idx], o;
        float lnx;
        lnx = (xv[i].x - mu) * rs * wv.x + bv.x; o.x = hv[i].x + g * (lnx - hv[i].x);
        lnx = (xv[i].y - mu) * rs * wv.y + bv.y; o.y = hv[i].y + g * (lnx - hv[i].y);
        lnx = (xv[i].z - mu) * rs * wv.z + bv.z; o.z = hv[i].z + g * (lnx - hv[i].z);
        lnx = (xv[i].w - mu) * rs * wv.w + bv.w; o.w = hv[i].w + g * (lnx - hv[i].w);
        orow[idx] = o;
    }
}

// ---------------------------------------------------------------------------
// Launch
// ---------------------------------------------------------------------------
extern "C" void kernel_launch(void* const* d_in, const int* in_sizes, int n_in,
                              void* d_out, int out_size) {
    const float* hidden = (const float*)d_in[0];
    const float* mem    = (const float*)d_in[1];
    const unsigned char* mask = (const unsigned char*)d_in[2];
    const float* Wq = (const float*)d_in[3];
    const float* bq = (const float*)d_in[4];
    const float* Wk = (const float*)d_in[5];
    const float* bk = (const float*)d_in[6];
    const float* Wv = (const float*)d_in[7];
    const float* bv = (const float*)d_in[8];
    const float* Wo = (const float*)d_in[9];
    const float* bo = (const float*)d_in[10];
    const float* ln_in_w  = (const float*)d_in[11];
    const float* ln_in_b  = (const float*)d_in[12];
    const float* ln_out_w = (const float*)d_in[13];
    const float* ln_out_b = (const float*)d_in[14];
    const float* gate     = (const float*)d_in[15];
    float* out = (float*)d_out;

    __nv_bfloat16 *p_hnorm, *p_memc, *p_q, *p_k, *p_vt, *p_pb, *p_ctx;
    __nv_bfloat16 *p_wqt, *p_wkt, *p_wvt, *p_wot;
    float *p_v, *p_s, *p_ch;
    cudaGetSymbolAddress((void**)&p_hnorm, g_hnorm);
    cudaGetSymbolAddress((void**)&p_memc, g_memc);
    cudaGetSymbolAddress((void**)&p_q,   g_q);
    cudaGetSymbolAddress((void**)&p_k,   g_k);
    cudaGetSymbolAddress((void**)&p_v,   g_v);
    cudaGetSymbolAddress((void**)&p_vt,  g_vt);
    cudaGetSymbolAddress((void**)&p_s,   g_s);
    cudaGetSymbolAddress((void**)&p_pb,  g_pb);
    cudaGetSymbolAddress((void**)&p_ctx, g_ctx);
    cudaGetSymbolAddress((void**)&p_ch,  g_ch);
    cudaGetSymbolAddress((void**)&p_wqt, g_wqt);
    cudaGetSymbolAddress((void**)&p_wkt, g_wkt);
    cudaGetSymbolAddress((void**)&p_wvt, g_wvt);
    cudaGetSymbolAddress((void**)&p_wot, g_wot);

    const int SMEM_GEMM = 3 * STAGE_BYTES;   // 98304 B
    cudaFuncSetAttribute(gemm_mma, cudaFuncAttributeMaxDynamicSharedMemorySize, SMEM_GEMM);

    const float scale = 0.044194173824159216f;  // 1/sqrt(512)

    // producers (bf16 outputs)
    ln_in_kernel<<<QROWS, 256>>>(hidden, ln_in_w, ln_in_b, p_hnorm);
    cvt_copy_kernel<<<(Bsz * TMd * Ddim / 4 + 255) / 256, 256>>>(
        (const float4*)mem, (__nv_bfloat162*)p_memc, Bsz * TMd * Ddim / 4);
    transpose_kernel<<<dim3(16, 128, 1), dim3(32, 8)>>>(Wq, p_wqt, Hdim, Adim, 0, 0);
    transpose_kernel<<<dim3(16, 32, 1),  dim3(32, 8)>>>(Wk, p_wkt, Ddim, Adim, 0, 0);
    transpose_kernel<<<dim3(16, 32, 1),  dim3(32, 8)>>>(Wv, p_wvt, Ddim, Adim, 0, 0);
    transpose_kernel<<<dim3(128, 16, 1), dim3(32, 8)>>>(Wo, p_wot, Adim, Hdim, 0, 0);

    // Q = hnorm @ Wq + bq                [8192,512]  K=4096   -> bf16
    gemm_mma<<<dim3(4, 64, 1), 256, SMEM_GEMM>>>(
        p_hnorm, p_wqt, bq, p_q, QROWS, Hdim, Adim, 0, 0, 0, 1.f, 1);

    // K = mem @ Wk + bk   (per batch, M=1500 -> 1536)          -> bf16
    gemm_mma<<<dim3(4, 12, Bsz), 256, SMEM_GEMM>>>(
        p_memc, p_wkt, bk, p_k, TMd, Ddim, Adim,
        (long)TMd * Ddim, 0, (long)TMp * Adim, 1.f, 1);

    // V = mem @ Wv + bv                                        -> fp32
    gemm_mma<<<dim3(4, 12, Bsz), 256, SMEM_GEMM>>>(
        p_memc, p_wvt, bv, p_v, TMd, Ddim, Adim,
        (long)TMd * Ddim, 0, (long)TMp * Adim, 1.f, 0);

    // V^T per batch: [1536,512] -> [512,1536]                  -> bf16
    transpose_kernel<<<dim3(16, 48, Bsz), dim3(32, 8)>>>(
        p_v, p_vt, TMp, Adim, (long)TMp * Adim, (long)Adim * TMp);

    // scores = scale * Q @ K^T           per batch [2048,1536] K=512  -> fp32
    gemm_mma<<<dim3(12, 16, Bsz), 256, SMEM_GEMM>>>(
        p_q, p_k, nullptr, p_s, LQd, Adim, TMp,
        (long)LQd * Adim, (long)TMp * Adim, (long)LQd * TMp, scale, 0);

    // softmax (masked) -> bf16 probs (pad cols zero)
    softmax_kernel<<<QROWS, 256>>>(p_s, mask, p_pb);

    // context = P @ V                    per batch [2048,512] K=1536  -> bf16
    gemm_mma<<<dim3(4, 16, Bsz), 256, SMEM_GEMM>>>(
        p_pb, p_vt, nullptr, p_ctx, LQd, TMp, Adim,
        (long)LQd * TMp, (long)Adim * TMp, (long)LQd * Adim, 1.f, 1);

    // context_h = context @ Wo + bo      [8192,4096]  K=512    -> fp32
    gemm_mma<<<dim3(32, 64, 1), 256, SMEM_GEMM>>>(
        p_ctx, p_wot, bo, p_ch, QROWS, Adim, Hdim, 0, 0, 0, 1.f, 0);

    // out
    final_kernel<<<QROWS, 256>>>(hidden, p_ch, ln_out_w, ln_out_b, gate, out);
}

// round 5
// speedup vs baseline: 6.2016x; 1.0368x over previous
#include <cuda_runtime.h>
#include <cuda_bf16.h>
#include <math.h>
#include <stdint.h>

// Problem dims
#define Hdim 4096
#define Ddim 1024
#define Adim 512
#define Bsz  4
#define LQd  2048
#define TMd  1500
#define TMp  1536

#define QROWS (Bsz * LQd)    // 8192

// ---------------------------------------------------------------------------
// Scratch
// ---------------------------------------------------------------------------
__device__ __nv_bfloat16 g_hnorm[(size_t)QROWS * Hdim];
__device__ __nv_bfloat16 g_memc [(size_t)Bsz * TMd * Ddim];
__device__ __nv_bfloat16 g_q    [(size_t)QROWS * Adim];
__device__ __nv_bfloat16 g_k    [(size_t)Bsz * TMp * Adim];
__device__ float         g_v    [(size_t)Bsz * TMp * Adim];
__device__ __nv_bfloat16 g_vt   [(size_t)Bsz * Adim * TMp];
__device__ float         g_s    [(size_t)Bsz * LQd * TMp];
__device__ __nv_bfloat16 g_pb   [(size_t)Bsz * LQd * TMp];
__device__ __nv_bfloat16 g_ctx  [(size_t)QROWS * Adim];
__device__ float         g_ch   [(size_t)QROWS * Hdim];
__device__ __nv_bfloat16 g_wqt  [(size_t)Adim * Hdim];
__device__ __nv_bfloat16 g_wkt  [(size_t)Adim * Ddim];
__device__ __nv_bfloat16 g_wvt  [(size_t)Adim * Ddim];
__device__ __nv_bfloat16 g_wot  [(size_t)Hdim * Adim];

// ---------------------------------------------------------------------------
// Helpers
// ---------------------------------------------------------------------------
__device__ __forceinline__ uint32_t smem_u32(const void* p) {
    uint32_t a;
    asm("{ .reg .u64 t; cvta.to.shared.u64 t, %1; cvt.u32.u64 %0, t; }" : "=r"(a) : "l"(p));
    return a;
}

__device__ __forceinline__ void cp_async16(uint32_t dst, const void* src, int sz) {
    asm volatile("cp.async.cg.shared.global [%0], [%1], 16, %2;"
        :: "r"(dst), "l"(src), "r"(sz) : "memory");
}
__device__ __forceinline__ void cp_commit() {
    asm volatile("cp.async.commit_group;" ::: "memory");
}
__device__ __forceinline__ void cp_wait2() {
    asm volatile("cp.async.wait_group 2;" ::: "memory");
}

__device__ __forceinline__ void ldsm4(uint32_t* r, uint32_t addr) {
    asm volatile("ldmatrix.sync.aligned.m8n8.x4.shared.b16 {%0,%1,%2,%3}, [%4];"
        : "=r"(r[0]), "=r"(r[1]), "=r"(r[2]), "=r"(r[3]) : "r"(addr));
}

__device__ __forceinline__ void mma_bf16(float* c, const uint32_t* a, const uint32_t* b) {
    asm volatile(
        "mma.sync.aligned.m16n8k16.row.col.f32.bf16.bf16.f32 "
        "{%0,%1,%2,%3}, {%4,%5,%6,%7}, {%8,%9}, {%0,%1,%2,%3};"
        : "+f"(c[0]), "+f"(c[1]), "+f"(c[2]), "+f"(c[3])
        : "r"(a[0]), "r"(a[1]), "r"(a[2]), "r"(a[3]), "r"(b[0]), "r"(b[1]));
}

// ---------------------------------------------------------------------------
// bf16 mma.sync GEMM:  C[M,N] = alpha * A[M,K] @ B[N,K]^T + bias
//   128x128x64 CTA tile, 8 warps (4x2), triple-buffered cp.async pipeline,
//   16B-granule XOR swizzle, ldmatrix.x4 fragment loads (conflict-free).
//   A rows >= Mvalid read as zero (cp.async src-size 0).
// ---------------------------------------------------------------------------
#define STAGE_BYTES 32768     // 16KB A + 16KB B (128 rows x 128B each)

__global__ __launch_bounds__(256, 2)
void gemm_mma(const __nv_bfloat16* __restrict__ Ag, const __nv_bfloat16* __restrict__ Bg,
              const float* __restrict__ bias, void* __restrict__ Cg,
              int Mvalid, int K, int ldc, long sA, long sB, long sC,
              float alpha, int outBF16)
{
    extern __shared__ char sm[];   // 3 * STAGE_BYTES

    const int tid = threadIdx.x;
    const int wid = tid >> 5, lane = tid & 31;
    const int lq = lane >> 2, lm4 = lane & 3;
    const int wm = wid & 3, wn = wid >> 2;
    const int row0 = blockIdx.y * 128;
    const int col0 = blockIdx.x * 128;
    const __nv_bfloat16* A = Ag + (long)blockIdx.z * sA;
    const __nv_bfloat16* B = Bg + (long)blockIdx.z * sB;
    const int NC = K >> 6;         // 64 elements per chunk
    const uint32_t sbase = smem_u32(sm);

    // loader: 4 (row, granule) pairs per matrix per thread
    auto load_stage = [&](int s, int kc) {
        uint32_t As = sbase + s * STAGE_BYTES;
        uint32_t Bs = As + 16384;
        #pragma unroll
        for (int i = 0; i < 4; i++) {
            int idx = tid + i * 256;            // 0..1023
            int r = idx >> 3, g = idx & 7;
            int dst = r * 128 + ((g ^ (r & 7)) << 4);
            int szA = (row0 + r < Mvalid) ? 16 : 0;
            cp_async16(As + dst, A + (size_t)(row0 + r) * K + kc + g * 8, szA);
            cp_async16(Bs + dst, B + (size_t)(col0 + r) * K + kc + g * 8, 16);
        }
    };

    float acc[2][8][4];
    #pragma unroll
    for (int mt = 0; mt < 2; mt++)
        #pragma unroll
        for (int nt = 0; nt < 8; nt++)
            #pragma unroll
            for (int e = 0; e < 4; e++) acc[mt][nt][e] = 0.f;

    load_stage(0, 0); cp_commit();
    if (NC > 1) load_stage(1, 64);
    cp_commit();

    // ldmatrix per-lane base addresses (stage 0)
    const int lj8 = lane & 7;       // row-within-8 this lane addresses
    const int mi  = lane >> 3;      // matrix index 0..3
    const int agb = mi >> 1;        // A granule bit
    const int bgb = mi & 1;         // B granule bit
    uint32_t aab[2], bab[4];
    #pragma unroll
    for (int mt = 0; mt < 2; mt++)
        aab[mt] = sbase + (uint32_t)(wm * 32 + mt * 16 + ((mi & 1) << 3) + lj8) * 128;
    #pragma unroll
    for (int p = 0; p < 4; p++)
        bab[p] = sbase + 16384u + (uint32_t)(wn * 64 + p * 16 + ((mi >> 1) << 3) + lj8) * 128;

    for (int c = 0; c < NC; ++c) {
        int nc = c + 2;
        if (nc < NC) load_stage(nc % 3, nc * 64);
        cp_commit();
        cp_wait2();
        __syncthreads();

        const uint32_t soff = (uint32_t)(c % 3) * STAGE_BYTES;

        #pragma unroll
        for (int ks = 0; ks < 4; ++ks) {
            const uint32_t axo = (uint32_t)(((2 * ks + agb) ^ lj8) << 4) + soff;
            const uint32_t bxo = (uint32_t)(((2 * ks + bgb) ^ lj8) << 4) + soff;
            uint32_t a[2][4], b[4][4];
            ldsm4(a[0], aab[0] + axo);
            ldsm4(a[1], aab[1] + axo);
            #pragma unroll
            for (int p = 0; p < 4; p++) ldsm4(b[p], bab[p] + bxo);
            #pragma unroll
            for (int mt = 0; mt < 2; mt++)
                #pragma unroll
                for (int nt = 0; nt < 8; nt++)
                    mma_bf16(acc[mt][nt], a[mt], &b[nt >> 1][(nt & 1) * 2]);
        }
        __syncthreads();
    }

    // epilogue
    #pragma unroll
    for (int mt = 0; mt < 2; mt++) {
        int rg = row0 + wm * 32 + mt * 16 + lq;
        #pragma unroll
        for (int nt = 0; nt < 8; nt++) {
            int cg = col0 + wn * 64 + nt * 8 + 2 * lm4;
            float2 bv = make_float2(0.f, 0.f);
            if (bias) bv = __ldg(reinterpret_cast<const float2*>(bias + cg));
            float2 v0, v1;
            v0.x = acc[mt][nt][0] * alpha + bv.x;
            v0.y = acc[mt][nt][1] * alpha + bv.y;
            v1.x = acc[mt][nt][2] * alpha + bv.x;
            v1.y = acc[mt][nt][3] * alpha + bv.y;
            if (outBF16) {
                __nv_bfloat16* C = (__nv_bfloat16*)Cg + (long)blockIdx.z * sC;
                *reinterpret_cast<__nv_bfloat162*>(C + (size_t)rg * ldc + cg) =
                    __floats2bfloat162_rn(v0.x, v0.y);
                *reinterpret_cast<__nv_bfloat162*>(C + (size_t)(rg + 8) * ldc + cg) =
                    __floats2bfloat162_rn(v1.x, v1.y);
            } else {
                float* C = (float*)Cg + (long)blockIdx.z * sC;
                *reinterpret_cast<float2*>(C + (size_t)rg * ldc + cg) = v0;
                *reinterpret_cast<float2*>(C + (size_t)(rg + 8) * ldc + cg) = v1;
            }
        }
    }
}

// ---------------------------------------------------------------------------
// Transpose: out[C,R] = bf16(in[R,C]^T)
// ---------------------------------------------------------------------------
__global__ void transpose_kernel(const float* __restrict__ in, __nv_bfloat16* __restrict__ out,
                                 int R, int C, long inB, long outB) {
    __shared__ float t[32][33];
    const float* ip = in + (long)blockIdx.z * inB;
    __nv_bfloat16* op = out + (long)blockIdx.z * outB;
    int r0 = blockIdx.y * 32, c0 = blockIdx.x * 32;
    int x = threadIdx.x, y = threadIdx.y;
    #pragma unroll
    for (int i = 0; i < 32; i += 8)
        t[y + i][x] = ip[(long)(r0 + y + i) * C + c0 + x];
    __syncthreads();
    #pragma unroll
    for (int i = 0; i < 32; i += 8)
        op[(long)(c0 + y + i) * R + r0 + x] = __float2bfloat16(t[x][y + i]);
}

// ---------------------------------------------------------------------------
// fp32 -> bf16 copy
// ---------------------------------------------------------------------------
__global__ void cvt_copy_kernel(const float4* __restrict__ in,
                                __nv_bfloat162* __restrict__ out, int n4) {
    int i = blockIdx.x * blockDim.x + threadIdx.x;
    if (i < n4) {
        float4 v = in[i];
        out[2 * i]     = __floats2bfloat162_rn(v.x, v.y);
        out[2 * i + 1] = __floats2bfloat162_rn(v.z, v.w);
    }
}

// ---------------------------------------------------------------------------
// Block reductions (256 threads)
// ---------------------------------------------------------------------------
__device__ __forceinline__ void block_sum2(float& s, float& ss) {
    #pragma unroll
    for (int o = 16; o > 0; o >>= 1) {
        s  += __shfl_xor_sync(0xffffffffu, s,  o);
        ss += __shfl_xor_sync(0xffffffffu, ss, o);
    }
    __shared__ float sh1[8], sh2[8];
    int wid = threadIdx.x >> 5;
    if ((threadIdx.x & 31) == 0) { sh1[wid] = s; sh2[wid] = ss; }
    __syncthreads();
    s = 0.f; ss = 0.f;
    #pragma unroll
    for (int i = 0; i < 8; i++) { s += sh1[i]; ss += sh2[i]; }
}

__device__ __forceinline__ float block_max256(float v) {
    #pragma unroll
    for (int o = 16; o > 0; o >>= 1)
        v = fmaxf(v, __shfl_xor_sync(0xffffffffu, v, o));
    __shared__ float shm[8];
    int wid = threadIdx.x >> 5;
    if ((threadIdx.x & 31) == 0) shm[wid] = v;
    __syncthreads();
    v = -3.4e38f;
    #pragma unroll
    for (int i = 0; i < 8; i++) v = fmaxf(v, shm[i]);
    return v;
}

__device__ __forceinline__ float block_sum256(float v) {
    #pragma unroll
    for (int o = 16; o > 0; o >>= 1)
        v += __shfl_xor_sync(0xffffffffu, v, o);
    __shared__ float shs[8];
    int wid = threadIdx.x >> 5;
    if ((threadIdx.x & 31) == 0) shs[wid] = v;
    __syncthreads();
    v = 0.f;
    #pragma unroll
    for (int i = 0; i < 8; i++) v += shs[i];
    return v;
}

// ---------------------------------------------------------------------------
// Input LayerNorm (bf16 output)
// ---------------------------------------------------------------------------
__global__ void ln_in_kernel(const float* __restrict__ x, const float* __restrict__ w,
                             const float* __restrict__ b, __nv_bfloat16* __restrict__ y) {
    const size_t row = blockIdx.x;
    const float4* xr = reinterpret_cast<const float4*>(x + row * Hdim);
    const float4* wr = reinterpret_cast<const float4*>(w);
    const float4* br = reinterpret_cast<const float4*>(b);
    __nv_bfloat162* yr = reinterpret_cast<__nv_bfloat162*>(y + row * Hdim);

    float4 v[4];
    float s = 0.f, ss = 0.f;
    #pragma unroll
    for (int i = 0; i < 4; i++) {
        v[i] = xr[threadIdx.x + i * 256];
        s  += v[i].x + v[i].y + v[i].z + v[i].w;
        ss += v[i].x * v[i].x + v[i].y * v[i].y + v[i].z * v[i].z + v[i].w * v[i].w;
    }
    block_sum2(s, ss);
    const float mu  = s * (1.f / Hdim);
    const float var = ss * (1.f / Hdim) - mu * mu;
    const float rs  = rsqrtf(var + 1e-5f);
    #pragma unroll
    for (int i = 0; i < 4; i++) {
        int idx = threadIdx.x + i * 256;
        float4 wv = wr[idx], bv = br[idx];
        float ox = (v[i].x - mu) * rs * wv.x + bv.x;
        float oy = (v[i].y - mu) * rs * wv.y + bv.y;
        float oz = (v[i].z - mu) * rs * wv.z + bv.z;
        float ow = (v[i].w - mu) * rs * wv.w + bv.w;
        yr[2 * idx]     = __floats2bfloat162_rn(ox, oy);
        yr[2 * idx + 1] = __floats2bfloat162_rn(oz, ow);
    }
}

// ---------------------------------------------------------------------------
// Masked softmax: read fp32 scores (stride TMp), write bf16 probs (stride TMp)
// ---------------------------------------------------------------------------
__global__ void softmax_kernel(const float* __restrict__ S, const unsigned char* __restrict__ mask,
                               __nv_bfloat16* __restrict__ P) {
    const int b = blockIdx.x >> 11;
    const float* row = S + (size_t)blockIdx.x * TMp;
    __nv_bfloat16* prow = P + (size_t)blockIdx.x * TMp;
    const unsigned char* mrow = mask + (size_t)b * TMd;

    float vals[6];
    float mx = -3.4e38f;
    #pragma unroll
    for (int i = 0; i < 6; i++) {
        int idx = threadIdx.x + i * 256;
        if (idx < TMd) {
            float v = row[idx];
            if (mrow[idx]) v = -1e30f;
            vals[i] = v;
            mx = fmaxf(mx, v);
        } else vals[i] = -3.4e38f;
    }
    mx = block_max256(mx);
    __syncthreads();

    float sum = 0.f;
    #pragma unroll
    for (int i = 0; i < 6; i++) {
        int idx = threadIdx.x + i * 256;
        if (idx < TMd) {
            float e = __expf(vals[i] - mx);
            vals[i] = e;
            sum += e;
        }
    }
    sum = block_sum256(sum);
    const float inv = 1.f / sum;

    #pragma unroll
    for (int i = 0; i < 6; i++) {
        int idx = threadIdx.x + i * 256;
        if (idx < TMd) prow[idx] = __float2bfloat16(vals[i] * inv);
        else if (idx < TMp) prow[idx] = __float2bfloat16(0.f);
    }
}

// ---------------------------------------------------------------------------
// Fused epilogue
// ---------------------------------------------------------------------------
__global__ void final_kernel(const float* __restrict__ h, const float* __restrict__ ch,
                             const float* __restrict__ w, const float* __restrict__ b,
                             const float* __restrict__ gate, float* __restrict__ out) {
    const size_t row = blockIdx.x;
    const float4* hr = reinterpret_cast<const float4*>(h + row * Hdim);
    const float4* cr = reinterpret_cast<const float4*>(ch + row * Hdim);
    const float4* wr = reinterpret_cast<const float4*>(w);
    const float4* br = reinterpret_cast<const float4*>(b);
    float4* orow = reinterpret_cast<float4*>(out + row * Hdim);

    float4 hv[4], xv[4];
    float s = 0.f, ss = 0.f;
    #pragma unroll
    for (int i = 0; i < 4; i++) {
        hv[i] = hr[threadIdx.x + i * 256];
        float4 cv = cr[threadIdx.x + i * 256];
        xv[i].x = hv[i].x + cv.x;
        xv[i].y = hv[i].y + cv.y;
        xv[i].z = hv[i].z + cv.z;
        xv[i].w = hv[i].w + cv.w;
        s  += xv[i].x + xv[i].y + xv[i].z + xv[i].w;
        ss += xv[i].x * xv[i].x + xv[i].y * xv[i].y + xv[i].z * xv[i].z + xv[i].w * xv[i].w;
    }
    block_sum2(s, ss);
    const float mu  = s * (1.f / Hdim);
    const float var = ss * (1.f / Hdim) - mu * mu;
    const float rs  = rsqrtf(var + 1e-5f);
    const float g   = 1.f / (1.f + expf(-gate[0]));

    #pragma unroll
    for (int i = 0; i < 4; i++) {
        int idx = threadIdx.x + i * 256;
        float4 wv = wr[idx], bv = br[idx], o;
        float lnx;
        lnx = (xv[i].x - mu) * rs * wv.x + bv.x; o.x = hv[i].x + g * (lnx - hv[i].x);
        lnx = (xv[i].y - mu) * rs * wv.y + bv.y; o.y = hv[i].y + g * (lnx - hv[i].y);
        lnx = (xv[i].z - mu) * rs * wv.z + bv.z; o.z = hv[i].z + g * (lnx - hv[i].z);
        lnx = (xv[i].w - mu) * rs * wv.w + bv.w; o.w = hv[i].w + g * (lnx - hv[i].w);
        orow[idx] = o;
    }
}

// ---------------------------------------------------------------------------
// Launch
// ---------------------------------------------------------------------------
extern "C" void kernel_launch(void* const* d_in, const int* in_sizes, int n_in,
                              void* d_out, int out_size) {
    const float* hidden = (const float*)d_in[0];
    const float* mem    = (const float*)d_in[1];
    const unsigned char* mask = (const unsigned char*)d_in[2];
    const float* Wq = (const float*)d_in[3];
    const float* bq = (const float*)d_in[4];
    const float* Wk = (const float*)d_in[5];
    const float* bk = (const float*)d_in[6];
    const float* Wv = (const float*)d_in[7];
    const float* bv = (const float*)d_in[8];
    const float* Wo = (const float*)d_in[9];
    const float* bo = (const float*)d_in[10];
    const float* ln_in_w  = (const float*)d_in[11];
    const float* ln_in_b  = (const float*)d_in[12];
    const float* ln_out_w = (const float*)d_in[13];
    const float* ln_out_b = (const float*)d_in[14];
    const float* gate     = (const float*)d_in[15];
    float* out = (float*)d_out;

    __nv_bfloat16 *p_hnorm, *p_memc, *p_q, *p_k, *p_vt, *p_pb, *p_ctx;
    __nv_bfloat16 *p_wqt, *p_wkt, *p_wvt, *p_wot;
    float *p_v, *p_s, *p_ch;
    cudaGetSymbolAddress((void**)&p_hnorm, g_hnorm);
    cudaGetSymbolAddress((void**)&p_memc, g_memc);
    cudaGetSymbolAddress((void**)&p_q,   g_q);
    cudaGetSymbolAddress((void**)&p_k,   g_k);
    cudaGetSymbolAddress((void**)&p_v,   g_v);
    cudaGetSymbolAddress((void**)&p_vt,  g_vt);
    cudaGetSymbolAddress((void**)&p_s,   g_s);
    cudaGetSymbolAddress((void**)&p_pb,  g_pb);
    cudaGetSymbolAddress((void**)&p_ctx, g_ctx);
    cudaGetSymbolAddress((void**)&p_ch,  g_ch);
    cudaGetSymbolAddress((void**)&p_wqt, g_wqt);
    cudaGetSymbolAddress((void**)&p_wkt, g_wkt);
    cudaGetSymbolAddress((void**)&p_wvt, g_wvt);
    cudaGetSymbolAddress((void**)&p_wot, g_wot);

    const int SMEM_GEMM = 3 * STAGE_BYTES;   // 98304 B
    cudaFuncSetAttribute(gemm_mma, cudaFuncAttributeMaxDynamicSharedMemorySize, SMEM_GEMM);

    const float scale = 0.044194173824159216f;  // 1/sqrt(512)

    // producers (bf16 outputs)
    ln_in_kernel<<<QROWS, 256>>>(hidden, ln_in_w, ln_in_b, p_hnorm);
    cvt_copy_kernel<<<(Bsz * TMd * Ddim / 4 + 255) / 256, 256>>>(
        (const float4*)mem, (__nv_bfloat162*)p_memc, Bsz * TMd * Ddim / 4);
    transpose_kernel<<<dim3(16, 128, 1), dim3(32, 8)>>>(Wq, p_wqt, Hdim, Adim, 0, 0);
    transpose_kernel<<<dim3(16, 32, 1),  dim3(32, 8)>>>(Wk, p_wkt, Ddim, Adim, 0, 0);
    transpose_kernel<<<dim3(16, 32, 1),  dim3(32, 8)>>>(Wv, p_wvt, Ddim, Adim, 0, 0);
    transpose_kernel<<<dim3(128, 16, 1), dim3(32, 8)>>>(Wo, p_wot, Adim, Hdim, 0, 0);

    // Q = hnorm @ Wq + bq                [8192,512]  K=4096   -> bf16
    gemm_mma<<<dim3(4, 64, 1), 256, SMEM_GEMM>>>(
        p_hnorm, p_wqt, bq, p_q, QROWS, Hdim, Adim, 0, 0, 0, 1.f, 1);

    // K = mem @ Wk + bk   (per batch, M=1500 -> 1536)          -> bf16
    gemm_mma<<<dim3(4, 12, Bsz), 256, SMEM_GEMM>>>(
        p_memc, p_wkt, bk, p_k, TMd, Ddim, Adim,
        (long)TMd * Ddim, 0, (long)TMp * Adim, 1.f, 1);

    // V = mem @ Wv + bv                                        -> fp32
    gemm_mma<<<dim3(4, 12, Bsz), 256, SMEM_GEMM>>>(
        p_memc, p_wvt, bv, p_v, TMd, Ddim, Adim,
        (long)TMd * Ddim, 0, (long)TMp * Adim, 1.f, 0);

    // V^T per batch: [1536,512] -> [512,1536]                  -> bf16
    transpose_kernel<<<dim3(16, 48, Bsz), dim3(32, 8)>>>(
        p_v, p_vt, TMp, Adim, (long)TMp * Adim, (long)Adim * TMp);

    // scores = scale * Q @ K^T           per batch [2048,1536] K=512  -> fp32
    gemm_mma<<<dim3(12, 16, Bsz), 256, SMEM_GEMM>>>(
        p_q, p_k, nullptr, p_s, LQd, Adim, TMp,
        (long)LQd * Adim, (long)TMp * Adim, (long)LQd * TMp, scale, 0);

    // softmax (masked) -> bf16 probs (pad cols zero)
    softmax_kernel<<<QROWS, 256>>>(p_s, mask, p_pb);

    // context = P @ V                    per batch [2048,512] K=1536  -> bf16
    gemm_mma<<<dim3(4, 16, Bsz), 256, SMEM_GEMM>>>(
        p_pb, p_vt, nullptr, p_ctx, LQd, TMp, Adim,
        (long)LQd * TMp, (long)Adim * TMp, (long)LQd * Adim, 1.f, 1);

    // context_h = context @ Wo + bo      [8192,4096]  K=512    -> fp32
    gemm_mma<<<dim3(32, 64, 1), 256, SMEM_GEMM>>>(
        p_ctx, p_wot, bo, p_ch, QROWS, Adim, Hdim, 0, 0, 0, 1.f, 0);

    // out
    final_kernel<<<QROWS, 256>>>(hidden, p_ch, ln_out_w, ln_out_b, gate, out);
}

// round 6
// speedup vs baseline: 6.3882x; 1.0301x over previous
#include <cuda_runtime.h>
#include <cuda_bf16.h>
#include <math.h>
#include <stdint.h>

// Problem dims
#define Hdim 4096
#define Ddim 1024
#define Adim 512
#define Bsz  4
#define LQd  2048
#define TMd  1500
#define TMp  1536

#define QROWS (Bsz * LQd)    // 8192

// ---------------------------------------------------------------------------
// Scratch
// ---------------------------------------------------------------------------
__device__ __nv_bfloat16 g_hnorm[(size_t)QROWS * Hdim];
__device__ __nv_bfloat16 g_memc [(size_t)Bsz * TMd * Ddim];
__device__ __nv_bfloat16 g_q    [(size_t)QROWS * Adim];
__device__ __nv_bfloat16 g_k    [(size_t)Bsz * TMp * Adim];
__device__ float         g_v    [(size_t)Bsz * TMp * Adim];
__device__ __nv_bfloat16 g_vt   [(size_t)Bsz * Adim * TMp];
__device__ float         g_s    [(size_t)Bsz * LQd * TMp];
__device__ __nv_bfloat16 g_pb   [(size_t)Bsz * LQd * TMp];
__device__ __nv_bfloat16 g_ctx  [(size_t)QROWS * Adim];
__device__ float         g_ch   [(size_t)QROWS * Hdim];
__device__ __nv_bfloat16 g_wqt  [(size_t)Adim * Hdim];
__device__ __nv_bfloat16 g_wkt  [(size_t)Adim * Ddim];
__device__ __nv_bfloat16 g_wvt  [(size_t)Adim * Ddim];
__device__ __nv_bfloat16 g_wot  [(size_t)Hdim * Adim];

// ---------------------------------------------------------------------------
// Helpers
// ---------------------------------------------------------------------------
__device__ __forceinline__ uint32_t smem_u32(const void* p) {
    uint32_t a;
    asm("{ .reg .u64 t; cvta.to.shared.u64 t, %1; cvt.u32.u64 %0, t; }" : "=r"(a) : "l"(p));
    return a;
}

__device__ __forceinline__ void cp_async16(uint32_t dst, const void* src, int sz) {
    asm volatile("cp.async.cg.shared.global [%0], [%1], 16, %2;"
        :: "r"(dst), "l"(src), "r"(sz) : "memory");
}
__device__ __forceinline__ void cp_commit() {
    asm volatile("cp.async.commit_group;" ::: "memory");
}
__device__ __forceinline__ void cp_wait2() {
    asm volatile("cp.async.wait_group 2;" ::: "memory");
}

__device__ __forceinline__ void ldsm4(uint32_t* r, uint32_t addr) {
    asm volatile("ldmatrix.sync.aligned.m8n8.x4.shared.b16 {%0,%1,%2,%3}, [%4];"
        : "=r"(r[0]), "=r"(r[1]), "=r"(r[2]), "=r"(r[3]) : "r"(addr));
}

__device__ __forceinline__ void mma_bf16(float* c, const uint32_t* a, const uint32_t* b) {
    asm volatile(
        "mma.sync.aligned.m16n8k16.row.col.f32.bf16.bf16.f32 "
        "{%0,%1,%2,%3}, {%4,%5,%6,%7}, {%8,%9}, {%0,%1,%2,%3};"
        : "+f"(c[0]), "+f"(c[1]), "+f"(c[2]), "+f"(c[3])
        : "r"(a[0]), "r"(a[1]), "r"(a[2]), "r"(a[3]), "r"(b[0]), "r"(b[1]));
}

// ---------------------------------------------------------------------------
// bf16 mma.sync GEMM:  C[M,N] = alpha * A[M,K] @ B[N,K]^T + bias
//   128x128x64 CTA tile, 4 warps (2x2) of 64x64 each, 128 threads.
//   Triple-buffered cp.async pipeline, 16B-granule XOR swizzle,
//   ldmatrix.x4 fragment loads. A rows >= Mvalid read as zero.
// ---------------------------------------------------------------------------
#define STAGE_BYTES 32768     // 16KB A + 16KB B (128 rows x 128B each)

__global__ __launch_bounds__(128)
void gemm_mma(const __nv_bfloat16* __restrict__ Ag, const __nv_bfloat16* __restrict__ Bg,
              const float* __restrict__ bias, void* __restrict__ Cg,
              int Mvalid, int K, int ldc, long sA, long sB, long sC,
              float alpha, int outBF16)
{
    extern __shared__ char sm[];   // 3 * STAGE_BYTES

    const int tid = threadIdx.x;
    const int wid = tid >> 5, lane = tid & 31;
    const int lq = lane >> 2, lm4 = lane & 3;
    const int wm = wid & 1, wn = wid >> 1;      // 2x2 warp grid, 64x64 tiles
    const int row0 = blockIdx.y * 128;
    const int col0 = blockIdx.x * 128;
    const __nv_bfloat16* A = Ag + (long)blockIdx.z * sA;
    const __nv_bfloat16* B = Bg + (long)blockIdx.z * sB;
    const int NC = K >> 6;         // 64 elements per chunk
    const uint32_t sbase = smem_u32(sm);

    // loader: 8 (row, granule) pairs per matrix per thread
    auto load_stage = [&](int s, int kc) {
        uint32_t As = sbase + s * STAGE_BYTES;
        uint32_t Bs = As + 16384;
        #pragma unroll
        for (int i = 0; i < 8; i++) {
            int idx = tid + i * 128;            // 0..1023
            int r = idx >> 3, g = idx & 7;
            int dst = r * 128 + ((g ^ (r & 7)) << 4);
            int szA = (row0 + r < Mvalid) ? 16 : 0;
            cp_async16(As + dst, A + (size_t)(row0 + r) * K + kc + g * 8, szA);
            cp_async16(Bs + dst, B + (size_t)(col0 + r) * K + kc + g * 8, 16);
        }
    };

    float acc[4][8][4];
    #pragma unroll
    for (int mt = 0; mt < 4; mt++)
        #pragma unroll
        for (int nt = 0; nt < 8; nt++)
            #pragma unroll
            for (int e = 0; e < 4; e++) acc[mt][nt][e] = 0.f;

    load_stage(0, 0); cp_commit();
    if (NC > 1) load_stage(1, 64);
    cp_commit();

    // ldmatrix per-lane base addresses
    const int lj8 = lane & 7;       // row-within-8 this lane addresses
    const int mi  = lane >> 3;      // matrix index 0..3
    const int agb = mi >> 1;        // A granule bit (k chunk select)
    const int bgb = mi & 1;         // B granule bit
    uint32_t aab[4], bab[4];
    #pragma unroll
    for (int p = 0; p < 4; p++)
        aab[p] = sbase + (uint32_t)(wm * 64 + p * 16 + ((mi & 1) << 3) + lj8) * 128;
    #pragma unroll
    for (int p = 0; p < 4; p++)
        bab[p] = sbase + 16384u + (uint32_t)(wn * 64 + p * 16 + ((mi >> 1) << 3) + lj8) * 128;

    for (int c = 0; c < NC; ++c) {
        int nc = c + 2;
        if (nc < NC) load_stage(nc % 3, nc * 64);
        cp_commit();
        cp_wait2();
        __syncthreads();

        const uint32_t soff = (uint32_t)(c % 3) * STAGE_BYTES;

        #pragma unroll
        for (int ks = 0; ks < 4; ++ks) {
            const uint32_t axo = (uint32_t)(((2 * ks + agb) ^ lj8) << 4) + soff;
            const uint32_t bxo = (uint32_t)(((2 * ks + bgb) ^ lj8) << 4) + soff;
            uint32_t a[4][4], b[4][4];
            #pragma unroll
            for (int p = 0; p < 4; p++) ldsm4(a[p], aab[p] + axo);
            #pragma unroll
            for (int p = 0; p < 4; p++) ldsm4(b[p], bab[p] + bxo);
            #pragma unroll
            for (int mt = 0; mt < 4; mt++)
                #pragma unroll
                for (int nt = 0; nt < 8; nt++)
                    mma_bf16(acc[mt][nt], a[mt], &b[nt >> 1][(nt & 1) * 2]);
        }
        __syncthreads();
    }

    // epilogue
    #pragma unroll
    for (int mt = 0; mt < 4; mt++) {
        int rg = row0 + wm * 64 + mt * 16 + lq;
        #pragma unroll
        for (int nt = 0; nt < 8; nt++) {
            int cg = col0 + wn * 64 + nt * 8 + 2 * lm4;
            float2 bv = make_float2(0.f, 0.f);
            if (bias) bv = __ldg(reinterpret_cast<const float2*>(bias + cg));
            float2 v0, v1;
            v0.x = acc[mt][nt][0] * alpha + bv.x;
            v0.y = acc[mt][nt][1] * alpha + bv.y;
            v1.x = acc[mt][nt][2] * alpha + bv.x;
            v1.y = acc[mt][nt][3] * alpha + bv.y;
            if (outBF16) {
                __nv_bfloat16* C = (__nv_bfloat16*)Cg + (long)blockIdx.z * sC;
                *reinterpret_cast<__nv_bfloat162*>(C + (size_t)rg * ldc + cg) =
                    __floats2bfloat162_rn(v0.x, v0.y);
                *reinterpret_cast<__nv_bfloat162*>(C + (size_t)(rg + 8) * ldc + cg) =
                    __floats2bfloat162_rn(v1.x, v1.y);
            } else {
                float* C = (float*)Cg + (long)blockIdx.z * sC;
                *reinterpret_cast<float2*>(C + (size_t)rg * ldc + cg) = v0;
                *reinterpret_cast<float2*>(C + (size_t)(rg + 8) * ldc + cg) = v1;
            }
        }
    }
}

// ---------------------------------------------------------------------------
// Transpose: out[C,R] = bf16(in[R,C]^T)
// ---------------------------------------------------------------------------
__global__ void transpose_kernel(const float* __restrict__ in, __nv_bfloat16* __restrict__ out,
                                 int R, int C, long inB, long outB) {
    __shared__ float t[32][33];
    const float* ip = in + (long)blockIdx.z * inB;
    __nv_bfloat16* op = out + (long)blockIdx.z * outB;
    int r0 = blockIdx.y * 32, c0 = blockIdx.x * 32;
    int x = threadIdx.x, y = threadIdx.y;
    #pragma unroll
    for (int i = 0; i < 32; i += 8)
        t[y + i][x] = ip[(long)(r0 + y + i) * C + c0 + x];
    __syncthreads();
    #pragma unroll
    for (int i = 0; i < 32; i += 8)
        op[(long)(c0 + y + i) * R + r0 + x] = __float2bfloat16(t[x][y + i]);
}

// ---------------------------------------------------------------------------
// fp32 -> bf16 copy
// ---------------------------------------------------------------------------
__global__ void cvt_copy_kernel(const float4* __restrict__ in,
                                __nv_bfloat162* __restrict__ out, int n4) {
    int i = blockIdx.x * blockDim.x + threadIdx.x;
    if (i < n4) {
        float4 v = in[i];
        out[2 * i]     = __floats2bfloat162_rn(v.x, v.y);
        out[2 * i + 1] = __floats2bfloat162_rn(v.z, v.w);
    }
}

// ---------------------------------------------------------------------------
// Block reductions (256 threads)
// ---------------------------------------------------------------------------
__device__ __forceinline__ void block_sum2(float& s, float& ss) {
    #pragma unroll
    for (int o = 16; o > 0; o >>= 1) {
        s  += __shfl_xor_sync(0xffffffffu, s,  o);
        ss += __shfl_xor_sync(0xffffffffu, ss, o);
    }
    __shared__ float sh1[8], sh2[8];
    int wid = threadIdx.x >> 5;
    if ((threadIdx.x & 31) == 0) { sh1[wid] = s; sh2[wid] = ss; }
    __syncthreads();
    s = 0.f; ss = 0.f;
    #pragma unroll
    for (int i = 0; i < 8; i++) { s += sh1[i]; ss += sh2[i]; }
}

__device__ __forceinline__ float block_max256(float v) {
    #pragma unroll
    for (int o = 16; o > 0; o >>= 1)
        v = fmaxf(v, __shfl_xor_sync(0xffffffffu, v, o));
    __shared__ float shm[8];
    int wid = threadIdx.x >> 5;
    if ((threadIdx.x & 31) == 0) shm[wid] = v;
    __syncthreads();
    v = -3.4e38f;
    #pragma unroll
    for (int i = 0; i < 8; i++) v = fmaxf(v, shm[i]);
    return v;
}

__device__ __forceinline__ float block_sum256(float v) {
    #pragma unroll
    for (int o = 16; o > 0; o >>= 1)
        v += __shfl_xor_sync(0xffffffffu, v, o);
    __shared__ float shs[8];
    int wid = threadIdx.x >> 5;
    if ((threadIdx.x & 31) == 0) shs[wid] = v;
    __syncthreads();
    v = 0.f;
    #pragma unroll
    for (int i = 0; i < 8; i++) v += shs[i];
    return v;
}

// ---------------------------------------------------------------------------
// Input LayerNorm (bf16 output)
// ---------------------------------------------------------------------------
__global__ void ln_in_kernel(const float* __restrict__ x, const float* __restrict__ w,
                             const float* __restrict__ b, __nv_bfloat16* __restrict__ y) {
    const size_t row = blockIdx.x;
    const float4* xr = reinterpret_cast<const float4*>(x + row * Hdim);
    const float4* wr = reinterpret_cast<const float4*>(w);
    const float4* br = reinterpret_cast<const float4*>(b);
    __nv_bfloat162* yr = reinterpret_cast<__nv_bfloat162*>(y + row * Hdim);

    float4 v[4];
    float s = 0.f, ss = 0.f;
    #pragma unroll
    for (int i = 0; i < 4; i++) {
        v[i] = xr[threadIdx.x + i * 256];
        s  += v[i].x + v[i].y + v[i].z + v[i].w;
        ss += v[i].x * v[i].x + v[i].y * v[i].y + v[i].z * v[i].z + v[i].w * v[i].w;
    }
    block_sum2(s, ss);
    const float mu  = s * (1.f / Hdim);
    const float var = ss * (1.f / Hdim) - mu * mu;
    const float rs  = rsqrtf(var + 1e-5f);
    #pragma unroll
    for (int i = 0; i < 4; i++) {
        int idx = threadIdx.x + i * 256;
        float4 wv = wr[idx], bv = br[idx];
        float ox = (v[i].x - mu) * rs * wv.x + bv.x;
        float oy = (v[i].y - mu) * rs * wv.y + bv.y;
        float oz = (v[i].z - mu) * rs * wv.z + bv.z;
        float ow = (v[i].w - mu) * rs * wv.w + bv.w;
        yr[2 * idx]     = __floats2bfloat162_rn(ox, oy);
        yr[2 * idx + 1] = __floats2bfloat162_rn(oz, ow);
    }
}

// ---------------------------------------------------------------------------
// Masked softmax: read fp32 scores (stride TMp), write bf16 probs (stride TMp)
// ---------------------------------------------------------------------------
__global__ void softmax_kernel(const float* __restrict__ S, const unsigned char* __restrict__ mask,
                               __nv_bfloat16* __restrict__ P) {
    const int b = blockIdx.x >> 11;
    const float* row = S + (size_t)blockIdx.x * TMp;
    __nv_bfloat16* prow = P + (size_t)blockIdx.x * TMp;
    const unsigned char* mrow = mask + (size_t)b * TMd;

    float vals[6];
    float mx = -3.4e38f;
    #pragma unroll
    for (int i = 0; i < 6; i++) {
        int idx = threadIdx.x + i * 256;
        if (idx < TMd) {
            float v = row[idx];
            if (mrow[idx]) v = -1e30f;
            vals[i] = v;
            mx = fmaxf(mx, v);
        } else vals[i] = -3.4e38f;
    }
    mx = block_max256(mx);
    __syncthreads();

    float sum = 0.f;
    #pragma unroll
    for (int i = 0; i < 6; i++) {
        int idx = threadIdx.x + i * 256;
        if (idx < TMd) {
            float e = __expf(vals[i] - mx);
            vals[i] = e;
            sum += e;
        }
    }
    sum = block_sum256(sum);
    const float inv = 1.f / sum;

    #pragma unroll
    for (int i = 0; i < 6; i++) {
        int idx = threadIdx.x + i * 256;
        if (idx < TMd) prow[idx] = __float2bfloat16(vals[i] * inv);
        else if (idx < TMp) prow[idx] = __float2bfloat16(0.f);
    }
}

// ---------------------------------------------------------------------------
// Fused epilogue
// ---------------------------------------------------------------------------
__global__ void final_kernel(const float* __restrict__ h, const float* __restrict__ ch,
                             const float* __restrict__ w, const float* __restrict__ b,
                             const float* __restrict__ gate, float* __restrict__ out) {
    const size_t row = blockIdx.x;
    const float4* hr = reinterpret_cast<const float4*>(h + row * Hdim);
    const float4* cr = reinterpret_cast<const float4*>(ch + row * Hdim);
    const float4* wr = reinterpret_cast<const float4*>(w);
    const float4* br = reinterpret_cast<const float4*>(b);
    float4* orow = reinterpret_cast<float4*>(out + row * Hdim);

    float4 hv[4], xv[4];
    float s = 0.f, ss = 0.f;
    #pragma unroll
    for (int i = 0; i < 4; i++) {
        hv[i] = hr[threadIdx.x + i * 256];
        float4 cv = cr[threadIdx.x + i * 256];
        xv[i].x = hv[i].x + cv.x;
        xv[i].y = hv[i].y + cv.y;
        xv[i].z = hv[i].z + cv.z;
        xv[i].w = hv[i].w + cv.w;
        s  += xv[i].x + xv[i].y + xv[i].z + xv[i].w;
        ss += xv[i].x * xv[i].x + xv[i].y * xv[i].y + xv[i].z * xv[i].z + xv[i].w * xv[i].w;
    }
    block_sum2(s, ss);
    const float mu  = s * (1.f / Hdim);
    const float var = ss * (1.f / Hdim) - mu * mu;
    const float rs  = rsqrtf(var + 1e-5f);
    const float g   = 1.f / (1.f + expf(-gate[0]));

    #pragma unroll
    for (int i = 0; i < 4; i++) {
        int idx = threadIdx.x + i * 256;
        float4 wv = wr[idx], bv = br[idx], o;
        float lnx;
        lnx = (xv[i].x - mu) * rs * wv.x + bv.x; o.x = hv[i].x + g * (lnx - hv[i].x);
        lnx = (xv[i].y - mu) * rs * wv.y + bv.y; o.y = hv[i].y + g * (lnx - hv[i].y);
        lnx = (xv[i].z - mu) * rs * wv.z + bv.z; o.z = hv[i].z + g * (lnx - hv[i].z);
        lnx = (xv[i].w - mu) * rs * wv.w + bv.w; o.w = hv[i].w + g * (lnx - hv[i].w);
        orow[idx] = o;
    }
}

// ---------------------------------------------------------------------------
// Launch
// ---------------------------------------------------------------------------
extern "C" void kernel_launch(void* const* d_in, const int* in_sizes, int n_in,
                              void* d_out, int out_size) {
    const float* hidden = (const float*)d_in[0];
    const float* mem    = (const float*)d_in[1];
    const unsigned char* mask = (const unsigned char*)d_in[2];
    const float* Wq = (const float*)d_in[3];
    const float* bq = (const float*)d_in[4];
    const float* Wk = (const float*)d_in[5];
    const float* bk = (const float*)d_in[6];
    const float* Wv = (const float*)d_in[7];
    const float* bv = (const float*)d_in[8];
    const float* Wo = (const float*)d_in[9];
    const float* bo = (const float*)d_in[10];
    const float* ln_in_w  = (const float*)d_in[11];
    const float* ln_in_b  = (const float*)d_in[12];
    const float* ln_out_w = (const float*)d_in[13];
    const float* ln_out_b = (const float*)d_in[14];
    const float* gate     = (const float*)d_in[15];
    float* out = (float*)d_out;

    __nv_bfloat16 *p_hnorm, *p_memc, *p_q, *p_k, *p_vt, *p_pb, *p_ctx;
    __nv_bfloat16 *p_wqt, *p_wkt, *p_wvt, *p_wot;
    float *p_v, *p_s, *p_ch;
    cudaGetSymbolAddress((void**)&p_hnorm, g_hnorm);
    cudaGetSymbolAddress((void**)&p_memc, g_memc);
    cudaGetSymbolAddress((void**)&p_q,   g_q);
    cudaGetSymbolAddress((void**)&p_k,   g_k);
    cudaGetSymbolAddress((void**)&p_v,   g_v);
    cudaGetSymbolAddress((void**)&p_vt,  g_vt);
    cudaGetSymbolAddress((void**)&p_s,   g_s);
    cudaGetSymbolAddress((void**)&p_pb,  g_pb);
    cudaGetSymbolAddress((void**)&p_ctx, g_ctx);
    cudaGetSymbolAddress((void**)&p_ch,  g_ch);
    cudaGetSymbolAddress((void**)&p_wqt, g_wqt);
    cudaGetSymbolAddress((void**)&p_wkt, g_wkt);
    cudaGetSymbolAddress((void**)&p_wvt, g_wvt);
    cudaGetSymbolAddress((void**)&p_wot, g_wot);

    const int SMEM_GEMM = 3 * STAGE_BYTES;   // 98304 B
    cudaFuncSetAttribute(gemm_mma, cudaFuncAttributeMaxDynamicSharedMemorySize, SMEM_GEMM);

    const float scale = 0.044194173824159216f;  // 1/sqrt(512)

    // producers (bf16 outputs)
    ln_in_kernel<<<QROWS, 256>>>(hidden, ln_in_w, ln_in_b, p_hnorm);
    cvt_copy_kernel<<<(Bsz * TMd * Ddim / 4 + 255) / 256, 256>>>(
        (const float4*)mem, (__nv_bfloat162*)p_memc, Bsz * TMd * Ddim / 4);
    transpose_kernel<<<dim3(16, 128, 1), dim3(32, 8)>>>(Wq, p_wqt, Hdim, Adim, 0, 0);
    transpose_kernel<<<dim3(16, 32, 1),  dim3(32, 8)>>>(Wk, p_wkt, Ddim, Adim, 0, 0);
    transpose_kernel<<<dim3(16, 32, 1),  dim3(32, 8)>>>(Wv, p_wvt, Ddim, Adim, 0, 0);
    transpose_kernel<<<dim3(128, 16, 1), dim3(32, 8)>>>(Wo, p_wot, Adim, Hdim, 0, 0);

    // Q = hnorm @ Wq + bq                [8192,512]  K=4096   -> bf16
    gemm_mma<<<dim3(4, 64, 1), 128, SMEM_GEMM>>>(
        p_hnorm, p_wqt, bq, p_q, QROWS, Hdim, Adim, 0, 0, 0, 1.f, 1);

    // K = mem @ Wk + bk   (per batch, M=1500 -> 1536)          -> bf16
    gemm_mma<<<dim3(4, 12, Bsz), 128, SMEM_GEMM>>>(
        p_memc, p_wkt, bk, p_k, TMd, Ddim, Adim,
        (long)TMd * Ddim, 0, (long)TMp * Adim, 1.f, 1);

    // V = mem @ Wv + bv                                        -> fp32
    gemm_mma<<<dim3(4, 12, Bsz), 128, SMEM_GEMM>>>(
        p_memc, p_wvt, bv, p_v, TMd, Ddim, Adim,
        (long)TMd * Ddim, 0, (long)TMp * Adim, 1.f, 0);

    // V^T per batch: [1536,512] -> [512,1536]                  -> bf16
    transpose_kernel<<<dim3(16, 48, Bsz), dim3(32, 8)>>>(
        p_v, p_vt, TMp, Adim, (long)TMp * Adim, (long)Adim * TMp);

    // scores = scale * Q @ K^T           per batch [2048,1536] K=512  -> fp32
    gemm_mma<<<dim3(12, 16, Bsz), 128, SMEM_GEMM>>>(
        p_q, p_k, nullptr, p_s, LQd, Adim, TMp,
        (long)LQd * Adim, (long)TMp * Adim, (long)LQd * TMp, scale, 0);

    // softmax (masked) -> bf16 probs (pad cols zero)
    softmax_kernel<<<QROWS, 256>>>(p_s, mask, p_pb);

    // context = P @ V                    per batch [2048,512] K=1536  -> bf16
    gemm_mma<<<dim3(4, 16, Bsz), 128, SMEM_GEMM>>>(
        p_pb, p_vt, nullptr, p_ctx, LQd, TMp, Adim,
        (long)LQd * TMp, (long)Adim * TMp, (long)LQd * Adim, 1.f, 1);

    // context_h = context @ Wo + bo      [8192,4096]  K=512    -> fp32
    gemm_mma<<<dim3(32, 64, 1), 128, SMEM_GEMM>>>(
        p_ctx, p_wot, bo, p_ch, QROWS, Adim, Hdim, 0, 0, 0, 1.f, 0);

    // out
    final_kernel<<<QROWS, 256>>>(hidden, p_ch, ln_out_w, ln_out_b, gate, out);
}

// round 7
// speedup vs baseline: 7.1627x; 1.1212x over previous
#include <cuda_runtime.h>
#include <cuda_bf16.h>
#include <math.h>
#include <stdint.h>

// Problem dims
#define Hdim 4096
#define Ddim 1024
#define Adim 512
#define Bsz  4
#define LQd  2048
#define TMd  1500
#define TMp  1536

#define QROWS (Bsz * LQd)    // 8192

// ---------------------------------------------------------------------------
// Scratch
// ---------------------------------------------------------------------------
__device__ __nv_bfloat16 g_hnorm[(size_t)QROWS * Hdim];
__device__ __nv_bfloat16 g_memc [(size_t)Bsz * TMd * Ddim];
__device__ __nv_bfloat16 g_q    [(size_t)QROWS * Adim];
__device__ __nv_bfloat16 g_k    [(size_t)Bsz * TMp * Adim];
__device__ __nv_bfloat16 g_v    [(size_t)Bsz * TMp * Adim];
__device__ __nv_bfloat16 g_vt   [(size_t)Bsz * Adim * TMp];
__device__ float         g_s    [(size_t)Bsz * LQd * TMp];
__device__ __nv_bfloat16 g_pb   [(size_t)Bsz * LQd * TMp];
__device__ __nv_bfloat16 g_ctx  [(size_t)QROWS * Adim];
__device__ __nv_bfloat16 g_ch   [(size_t)QROWS * Hdim];
__device__ __nv_bfloat16 g_wqt  [(size_t)Adim * Hdim];
__device__ __nv_bfloat16 g_wkt  [(size_t)Adim * Ddim];
__device__ __nv_bfloat16 g_wvt  [(size_t)Adim * Ddim];
__device__ __nv_bfloat16 g_wot  [(size_t)Hdim * Adim];

// ---------------------------------------------------------------------------
// Helpers
// ---------------------------------------------------------------------------
__device__ __forceinline__ uint32_t smem_u32(const void* p) {
    uint32_t a;
    asm("{ .reg .u64 t; cvta.to.shared.u64 t, %1; cvt.u32.u64 %0, t; }" : "=r"(a) : "l"(p));
    return a;
}

__device__ __forceinline__ void cp_async16(uint32_t dst, const void* src, int sz) {
    asm volatile("cp.async.cg.shared.global [%0], [%1], 16, %2;"
        :: "r"(dst), "l"(src), "r"(sz) : "memory");
}
__device__ __forceinline__ void cp_commit() {
    asm volatile("cp.async.commit_group;" ::: "memory");
}
__device__ __forceinline__ void cp_wait1() {
    asm volatile("cp.async.wait_group 1;" ::: "memory");
}

__device__ __forceinline__ void ldsm4(uint32_t* r, uint32_t addr) {
    asm volatile("ldmatrix.sync.aligned.m8n8.x4.shared.b16 {%0,%1,%2,%3}, [%4];"
        : "=r"(r[0]), "=r"(r[1]), "=r"(r[2]), "=r"(r[3]) : "r"(addr));
}

__device__ __forceinline__ void mma_bf16(float* c, const uint32_t* a, const uint32_t* b) {
    asm volatile(
        "mma.sync.aligned.m16n8k16.row.col.f32.bf16.bf16.f32 "
        "{%0,%1,%2,%3}, {%4,%5,%6,%7}, {%8,%9}, {%0,%1,%2,%3};"
        : "+f"(c[0]), "+f"(c[1]), "+f"(c[2]), "+f"(c[3])
        : "r"(a[0]), "r"(a[1]), "r"(a[2]), "r"(a[3]), "r"(b[0]), "r"(b[1]));
}

// ---------------------------------------------------------------------------
// GEMM segment descriptor
// ---------------------------------------------------------------------------
struct Seg {
    const __nv_bfloat16* A;
    const __nv_bfloat16* B;
    const float* bias;
    void* C;
    long sA, sB, sC;
    int Mvalid, K, ldc, outBF16;
    float alpha;
    int nx, ny;          // CTA grid within segment (for multi-launch)
};

// ---------------------------------------------------------------------------
// GEMM body:  C[128 rows @by, 128 cols @bx] = alpha * A @ B^T + bias
//   4 warps (2x2) of 64x64, triple-buffered cp.async, single-sync mainloop,
//   16B-granule XOR swizzle, ldmatrix.x4. A rows >= Mvalid read as zero.
// ---------------------------------------------------------------------------
#define STAGE_BYTES 32768     // 16KB A + 16KB B

__device__ __forceinline__ void gemm_body(const Seg& g, int bx, int by, int bz, char* sm)
{
    const int tid = threadIdx.x;
    const int wid = tid >> 5, lane = tid & 31;
    const int lq = lane >> 2, lm4 = lane & 3;
    const int wm = wid & 1, wn = wid >> 1;
    const int row0 = by * 128;
    const int col0 = bx * 128;
    const __nv_bfloat16* A = g.A + (long)bz * g.sA;
    const __nv_bfloat16* B = g.B + (long)bz * g.sB;
    const int K = g.K;
    const int Mvalid = g.Mvalid;
    const int NC = K >> 6;
    const uint32_t sbase = smem_u32(sm);

    auto load_stage = [&](int s, int kc) {
        uint32_t As = sbase + s * STAGE_BYTES;
        uint32_t Bs = As + 16384;
        #pragma unroll
        for (int i = 0; i < 8; i++) {
            int idx = tid + i * 128;
            int r = idx >> 3, gg = idx & 7;
            int dst = r * 128 + ((gg ^ (r & 7)) << 4);
            int szA = (row0 + r < Mvalid) ? 16 : 0;
            cp_async16(As + dst, A + (size_t)(row0 + r) * K + kc + gg * 8, szA);
            cp_async16(Bs + dst, B + (size_t)(col0 + r) * K + kc + gg * 8, 16);
        }
    };

    float acc[4][8][4];
    #pragma unroll
    for (int mt = 0; mt < 4; mt++)
        #pragma unroll
        for (int nt = 0; nt < 8; nt++)
            #pragma unroll
            for (int e = 0; e < 4; e++) acc[mt][nt][e] = 0.f;

    load_stage(0, 0); cp_commit();
    load_stage(1, 64); cp_commit();     // NC >= 2 always (K >= 128)

    const int lj8 = lane & 7;
    const int mi  = lane >> 3;
    const int agb = mi >> 1;
    const int bgb = mi & 1;
    uint32_t aab[4], bab[4];
    #pragma unroll
    for (int p = 0; p < 4; p++)
        aab[p] = sbase + (uint32_t)(wm * 64 + p * 16 + ((mi & 1) << 3) + lj8) * 128;
    #pragma unroll
    for (int p = 0; p < 4; p++)
        bab[p] = sbase + 16384u + (uint32_t)(wn * 64 + p * 16 + ((mi >> 1) << 3) + lj8) * 128;

    for (int c = 0; c < NC; ++c) {
        cp_wait1();            // stage c%3 data complete (this thread's groups)
        __syncthreads();       // all threads waited; all done computing c-1
        int nc = c + 2;
        if (nc < NC) load_stage(nc % 3, nc * 64);   // overwrites stage (c-1)%3: safe
        cp_commit();

        const uint32_t soff = (uint32_t)(c % 3) * STAGE_BYTES;
        #pragma unroll
        for (int ks = 0; ks < 4; ++ks) {
            const uint32_t axo = (uint32_t)(((2 * ks + agb) ^ lj8) << 4) + soff;
            const uint32_t bxo = (uint32_t)(((2 * ks + bgb) ^ lj8) << 4) + soff;
            uint32_t a[4][4], b[4][4];
            #pragma unroll
            for (int p = 0; p < 4; p++) ldsm4(a[p], aab[p] + axo);
            #pragma unroll
            for (int p = 0; p < 4; p++) ldsm4(b[p], bab[p] + bxo);
            #pragma unroll
            for (int mt = 0; mt < 4; mt++)
                #pragma unroll
                for (int nt = 0; nt < 8; nt++)
                    mma_bf16(acc[mt][nt], a[mt], &b[nt >> 1][(nt & 1) * 2]);
        }
    }

    // epilogue
    const float alpha = g.alpha;
    #pragma unroll
    for (int mt = 0; mt < 4; mt++) {
        int rg = row0 + wm * 64 + mt * 16 + lq;
        #pragma unroll
        for (int nt = 0; nt < 8; nt++) {
            int cg = col0 + wn * 64 + nt * 8 + 2 * lm4;
            float2 bv = make_float2(0.f, 0.f);
            if (g.bias) bv = __ldg(reinterpret_cast<const float2*>(g.bias + cg));
            float2 v0, v1;
            v0.x = acc[mt][nt][0] * alpha + bv.x;
            v0.y = acc[mt][nt][1] * alpha + bv.y;
            v1.x = acc[mt][nt][2] * alpha + bv.x;
            v1.y = acc[mt][nt][3] * alpha + bv.y;
            if (g.outBF16) {
                __nv_bfloat16* C = (__nv_bfloat16*)g.C + (long)bz * g.sC;
                *reinterpret_cast<__nv_bfloat162*>(C + (size_t)rg * g.ldc + cg) =
                    __floats2bfloat162_rn(v0.x, v0.y);
                *reinterpret_cast<__nv_bfloat162*>(C + (size_t)(rg + 8) * g.ldc + cg) =
                    __floats2bfloat162_rn(v1.x, v1.y);
            } else {
                float* C = (float*)g.C + (long)bz * g.sC;
                *reinterpret_cast<float2*>(C + (size_t)rg * g.ldc + cg) = v0;
                *reinterpret_cast<float2*>(C + (size_t)(rg + 8) * g.ldc + cg) = v1;
            }
        }
    }
}

// Single-segment GEMM
__global__ __launch_bounds__(128)
void gemm_one(const Seg g) {
    extern __shared__ char sm[];
    gemm_body(g, blockIdx.x, blockIdx.y, blockIdx.z, sm);
}

// Three independent segments in one launch (flat grid.x)
__global__ __launch_bounds__(128)
void gemm_multi(const Seg s0, const Seg s1, const Seg s2, int n0, int n1) {
    extern __shared__ char sm[];
    int id = blockIdx.x;
    Seg g;
    if (id < n0)            { g = s0; }
    else if (id < n0 + n1)  { g = s1; id -= n0; }
    else                    { g = s2; id -= n0 + n1; }
    int bx = id % g.nx;
    int by = (id / g.nx) % g.ny;
    int bz = id / (g.nx * g.ny);
    gemm_body(g, bx, by, bz, sm);
}

// ---------------------------------------------------------------------------
// Transpose fp32 -> bf16:  out[C,R] = bf16(in[R,C]^T)
// ---------------------------------------------------------------------------
__global__ void transpose_kernel(const float* __restrict__ in, __nv_bfloat16* __restrict__ out,
                                 int R, int C, long inB, long outB) {
    __shared__ float t[32][33];
    const float* ip = in + (long)blockIdx.z * inB;
    __nv_bfloat16* op = out + (long)blockIdx.z * outB;
    int r0 = blockIdx.y * 32, c0 = blockIdx.x * 32;
    int x = threadIdx.x, y = threadIdx.y;
    #pragma unroll
    for (int i = 0; i < 32; i += 8)
        t[y + i][x] = ip[(long)(r0 + y + i) * C + c0 + x];
    __syncthreads();
    #pragma unroll
    for (int i = 0; i < 32; i += 8)
        op[(long)(c0 + y + i) * R + r0 + x] = __float2bfloat16(t[x][y + i]);
}

// Transpose bf16 -> bf16
__global__ void transpose_b2b_kernel(const __nv_bfloat16* __restrict__ in,
                                     __nv_bfloat16* __restrict__ out,
                                     int R, int C, long inB, long outB) {
    __shared__ __nv_bfloat16 t[32][34];
    const __nv_bfloat16* ip = in + (long)blockIdx.z * inB;
    __nv_bfloat16* op = out + (long)blockIdx.z * outB;
    int r0 = blockIdx.y * 32, c0 = blockIdx.x * 32;
    int x = threadIdx.x, y = threadIdx.y;
    #pragma unroll
    for (int i = 0; i < 32; i += 8)
        t[y + i][x] = ip[(long)(r0 + y + i) * C + c0 + x];
    __syncthreads();
    #pragma unroll
    for (int i = 0; i < 32; i += 8)
        op[(long)(c0 + y + i) * R + r0 + x] = t[x][y + i];
}

// ---------------------------------------------------------------------------
// fp32 -> bf16 copy
// ---------------------------------------------------------------------------
__global__ void cvt_copy_kernel(const float4* __restrict__ in,
                                __nv_bfloat162* __restrict__ out, int n4) {
    int i = blockIdx.x * blockDim.x + threadIdx.x;
    if (i < n4) {
        float4 v = in[i];
        out[2 * i]     = __floats2bfloat162_rn(v.x, v.y);
        out[2 * i + 1] = __floats2bfloat162_rn(v.z, v.w);
    }
}

// ---------------------------------------------------------------------------
// Block reductions (256 threads)
// ---------------------------------------------------------------------------
__device__ __forceinline__ void block_sum2(float& s, float& ss) {
    #pragma unroll
    for (int o = 16; o > 0; o >>= 1) {
        s  += __shfl_xor_sync(0xffffffffu, s,  o);
        ss += __shfl_xor_sync(0xffffffffu, ss, o);
    }
    __shared__ float sh1[8], sh2[8];
    int wid = threadIdx.x >> 5;
    if ((threadIdx.x & 31) == 0) { sh1[wid] = s; sh2[wid] = ss; }
    __syncthreads();
    s = 0.f; ss = 0.f;
    #pragma unroll
    for (int i = 0; i < 8; i++) { s += sh1[i]; ss += sh2[i]; }
}

__device__ __forceinline__ float block_max256(float v) {
    #pragma unroll
    for (int o = 16; o > 0; o >>= 1)
        v = fmaxf(v, __shfl_xor_sync(0xffffffffu, v, o));
    __shared__ float shm[8];
    int wid = threadIdx.x >> 5;
    if ((threadIdx.x & 31) == 0) shm[wid] = v;
    __syncthreads();
    v = -3.4e38f;
    #pragma unroll
    for (int i = 0; i < 8; i++) v = fmaxf(v, shm[i]);
    return v;
}

__device__ __forceinline__ float block_sum256(float v) {
    #pragma unroll
    for (int o = 16; o > 0; o >>= 1)
        v += __shfl_xor_sync(0xffffffffu, v, o);
    __shared__ float shs[8];
    int wid = threadIdx.x >> 5;
    if ((threadIdx.x & 31) == 0) shs[wid] = v;
    __syncthreads();
    v = 0.f;
    #pragma unroll
    for (int i = 0; i < 8; i++) v += shs[i];
    return v;
}

// ---------------------------------------------------------------------------
// Input LayerNorm (bf16 output)
// ---------------------------------------------------------------------------
__global__ void ln_in_kernel(const float* __restrict__ x, const float* __restrict__ w,
                             const float* __restrict__ b, __nv_bfloat16* __restrict__ y) {
    const size_t row = blockIdx.x;
    const float4* xr = reinterpret_cast<const float4*>(x + row * Hdim);
    const float4* wr = reinterpret_cast<const float4*>(w);
    const float4* br = reinterpret_cast<const float4*>(b);
    __nv_bfloat162* yr = reinterpret_cast<__nv_bfloat162*>(y + row * Hdim);

    float4 v[4];
    float s = 0.f, ss = 0.f;
    #pragma unroll
    for (int i = 0; i < 4; i++) {
        v[i] = xr[threadIdx.x + i * 256];
        s  += v[i].x + v[i].y + v[i].z + v[i].w;
        ss += v[i].x * v[i].x + v[i].y * v[i].y + v[i].z * v[i].z + v[i].w * v[i].w;
    }
    block_sum2(s, ss);
    const float mu  = s * (1.f / Hdim);
    const float var = ss * (1.f / Hdim) - mu * mu;
    const float rs  = rsqrtf(var + 1e-5f);
    #pragma unroll
    for (int i = 0; i < 4; i++) {
        int idx = threadIdx.x + i * 256;
        float4 wv = wr[idx], bv = br[idx];
        float ox = (v[i].x - mu) * rs * wv.x + bv.x;
        float oy = (v[i].y - mu) * rs * wv.y + bv.y;
        float oz = (v[i].z - mu) * rs * wv.z + bv.z;
        float ow = (v[i].w - mu) * rs * wv.w + bv.w;
        yr[2 * idx]     = __floats2bfloat162_rn(ox, oy);
        yr[2 * idx + 1] = __floats2bfloat162_rn(oz, ow);
    }
}

// ---------------------------------------------------------------------------
// Masked softmax: fp32 scores (stride TMp) -> bf16 probs (stride TMp)
// ---------------------------------------------------------------------------
__global__ void softmax_kernel(const float* __restrict__ S, const unsigned char* __restrict__ mask,
                               __nv_bfloat16* __restrict__ P) {
    const int b = blockIdx.x >> 11;
    const float* row = S + (size_t)blockIdx.x * TMp;
    __nv_bfloat16* prow = P + (size_t)blockIdx.x * TMp;
    const unsigned char* mrow = mask + (size_t)b * TMd;

    float vals[6];
    float mx = -3.4e38f;
    #pragma unroll
    for (int i = 0; i < 6; i++) {
        int idx = threadIdx.x + i * 256;
        if (idx < TMd) {
            float v = row[idx];
            if (mrow[idx]) v = -1e30f;
            vals[i] = v;
            mx = fmaxf(mx, v);
        } else vals[i] = -3.4e38f;
    }
    mx = block_max256(mx);
    __syncthreads();

    float sum = 0.f;
    #pragma unroll
    for (int i = 0; i < 6; i++) {
        int idx = threadIdx.x + i * 256;
        if (idx < TMd) {
            float e = __expf(vals[i] - mx);
            vals[i] = e;
            sum += e;
        }
    }
    sum = block_sum256(sum);
    const float inv = 1.f / sum;

    #pragma unroll
    for (int i = 0; i < 6; i++) {
        int idx = threadIdx.x + i * 256;
        if (idx < TMd) prow[idx] = __float2bfloat16(vals[i] * inv);
        else if (idx < TMp) prow[idx] = __float2bfloat16(0.f);
    }
}

// ---------------------------------------------------------------------------
// Fused epilogue (ch in bf16)
// ---------------------------------------------------------------------------
__global__ void final_kernel(const float* __restrict__ h, const __nv_bfloat16* __restrict__ ch,
                             const float* __restrict__ w, const float* __restrict__ b,
                             const float* __restrict__ gate, float* __restrict__ out) {
    const size_t row = blockIdx.x;
    const float4* hr = reinterpret_cast<const float4*>(h + row * Hdim);
    const __nv_bfloat162* cr = reinterpret_cast<const __nv_bfloat162*>(ch + row * Hdim);
    const float4* wr = reinterpret_cast<const float4*>(w);
    const float4* br = reinterpret_cast<const float4*>(b);
    float4* orow = reinterpret_cast<float4*>(out + row * Hdim);

    float4 hv[4], xv[4];
    float s = 0.f, ss = 0.f;
    #pragma unroll
    for (int i = 0; i < 4; i++) {
        int idx = threadIdx.x + i * 256;
        hv[i] = hr[idx];
        float2 c0 = __bfloat1622float2(cr[2 * idx]);
        float2 c1 = __bfloat1622float2(cr[2 * idx + 1]);
        xv[i].x = hv[i].x + c0.x;
        xv[i].y = hv[i].y + c0.y;
        xv[i].z = hv[i].z + c1.x;
        xv[i].w = hv[i].w + c1.y;
        s  += xv[i].x + xv[i].y + xv[i].z + xv[i].w;
        ss += xv[i].x * xv[i].x + xv[i].y * xv[i].y + xv[i].z * xv[i].z + xv[i].w * xv[i].w;
    }
    block_sum2(s, ss);
    const float mu  = s * (1.f / Hdim);
    const float var = ss * (1.f / Hdim) - mu * mu;
    const float rs  = rsqrtf(var + 1e-5f);
    const float g   = 1.f / (1.f + expf(-gate[0]));

    #pragma unroll
    for (int i = 0; i < 4; i++) {
        int idx = threadIdx.x + i * 256;
        float4 wv = wr[idx], bv = br[idx], o;
        float lnx;
        lnx = (xv[i].x - mu) * rs * wv.x + bv.x; o.x = hv[i].x + g * (lnx - hv[i].x);
        lnx = (xv[i].y - mu) * rs * wv.y + bv.y; o.y = hv[i].y + g * (lnx - hv[i].y);
        lnx = (xv[i].z - mu) * rs * wv.z + bv.z; o.z = hv[i].z + g * (lnx - hv[i].z);
        lnx = (xv[i].w - mu) * rs * wv.w + bv.w; o.w = hv[i].w + g * (lnx - hv[i].w);
        orow[idx] = o;
    }
}

// ---------------------------------------------------------------------------
// Launch
// ---------------------------------------------------------------------------
extern "C" void kernel_launch(void* const* d_in, const int* in_sizes, int n_in,
                              void* d_out, int out_size) {
    const float* hidden = (const float*)d_in[0];
    const float* mem    = (const float*)d_in[1];
    const unsigned char* mask = (const unsigned char*)d_in[2];
    const float* Wq = (const float*)d_in[3];
    const float* bq = (const float*)d_in[4];
    const float* Wk = (const float*)d_in[5];
    const float* bk = (const float*)d_in[6];
    const float* Wv = (const float*)d_in[7];
    const float* bv = (const float*)d_in[8];
    const float* Wo = (const float*)d_in[9];
    const float* bo = (const float*)d_in[10];
    const float* ln_in_w  = (const float*)d_in[11];
    const float* ln_in_b  = (const float*)d_in[12];
    const float* ln_out_w = (const float*)d_in[13];
    const float* ln_out_b = (const float*)d_in[14];
    const float* gate     = (const float*)d_in[15];
    float* out = (float*)d_out;

    __nv_bfloat16 *p_hnorm, *p_memc, *p_q, *p_k, *p_v, *p_vt, *p_pb, *p_ctx, *p_ch;
    __nv_bfloat16 *p_wqt, *p_wkt, *p_wvt, *p_wot;
    float *p_s;
    cudaGetSymbolAddress((void**)&p_hnorm, g_hnorm);
    cudaGetSymbolAddress((void**)&p_memc, g_memc);
    cudaGetSymbolAddress((void**)&p_q,   g_q);
    cudaGetSymbolAddress((void**)&p_k,   g_k);
    cudaGetSymbolAddress((void**)&p_v,   g_v);
    cudaGetSymbolAddress((void**)&p_vt,  g_vt);
    cudaGetSymbolAddress((void**)&p_s,   g_s);
    cudaGetSymbolAddress((void**)&p_pb,  g_pb);
    cudaGetSymbolAddress((void**)&p_ctx, g_ctx);
    cudaGetSymbolAddress((void**)&p_ch,  g_ch);
    cudaGetSymbolAddress((void**)&p_wqt, g_wqt);
    cudaGetSymbolAddress((void**)&p_wkt, g_wkt);
    cudaGetSymbolAddress((void**)&p_wvt, g_wvt);
    cudaGetSymbolAddress((void**)&p_wot, g_wot);

    const int SMEM_GEMM = 3 * STAGE_BYTES;   // 98304 B
    cudaFuncSetAttribute(gemm_one,   cudaFuncAttributeMaxDynamicSharedMemorySize, SMEM_GEMM);
    cudaFuncSetAttribute(gemm_multi, cudaFuncAttributeMaxDynamicSharedMemorySize, SMEM_GEMM);

    const float scale = 0.044194173824159216f;  // 1/sqrt(512)

    // producers (bf16 outputs)
    ln_in_kernel<<<QROWS, 256>>>(hidden, ln_in_w, ln_in_b, p_hnorm);
    cvt_copy_kernel<<<(Bsz * TMd * Ddim / 4 + 255) / 256, 256>>>(
        (const float4*)mem, (__nv_bfloat162*)p_memc, Bsz * TMd * Ddim / 4);
    transpose_kernel<<<dim3(16, 128, 1), dim3(32, 8)>>>(Wq, p_wqt, Hdim, Adim, 0, 0);
    transpose_kernel<<<dim3(16, 32, 1),  dim3(32, 8)>>>(Wk, p_wkt, Ddim, Adim, 0, 0);
    transpose_kernel<<<dim3(16, 32, 1),  dim3(32, 8)>>>(Wv, p_wvt, Ddim, Adim, 0, 0);
    transpose_kernel<<<dim3(128, 16, 1), dim3(32, 8)>>>(Wo, p_wot, Adim, Hdim, 0, 0);

    // Merged launch: Q-proj (256 CTAs) + K (192) + V (192) = 640 CTAs
    Seg sq = { p_hnorm, p_wqt, bq, p_q, 0, 0, 0,
               QROWS, Hdim, Adim, 1, 1.f, 4, 64 };
    Seg sk = { p_memc, p_wkt, bk, p_k, (long)TMd * Ddim, 0, (long)TMp * Adim,
               TMd, Ddim, Adim, 1, 1.f, 4, 12 };
    Seg sv = { p_memc, p_wvt, bv, p_v, (long)TMd * Ddim, 0, (long)TMp * Adim,
               TMd, Ddim, Adim, 1, 1.f, 4, 12 };
    gemm_multi<<<640, 128, SMEM_GEMM>>>(sq, sk, sv, 256, 192);

    // V^T per batch: [1536,512] -> [512,1536]  (bf16 -> bf16)
    transpose_b2b_kernel<<<dim3(16, 48, Bsz), dim3(32, 8)>>>(
        p_v, p_vt, TMp, Adim, (long)TMp * Adim, (long)Adim * TMp);

    // scores = scale * Q @ K^T           per batch [2048,1536] K=512  -> fp32
    Seg sqk = { p_q, p_k, nullptr, p_s, (long)LQd * Adim, (long)TMp * Adim, (long)LQd * TMp,
                LQd, Adim, TMp, 0, scale, 12, 16 };
    gemm_one<<<dim3(12, 16, Bsz), 128, SMEM_GEMM>>>(sqk);

    // softmax (masked) -> bf16 probs (pad cols zero)
    softmax_kernel<<<QROWS, 256>>>(p_s, mask, p_pb);

    // context = P @ V                    per batch [2048,512] K=1536  -> bf16
    Seg spv = { p_pb, p_vt, nullptr, p_ctx, (long)LQd * TMp, (long)Adim * TMp, (long)LQd * Adim,
                LQd, TMp, Adim, 1, 1.f, 4, 16 };
    gemm_one<<<dim3(4, 16, Bsz), 128, SMEM_GEMM>>>(spv);

    // context_h = context @ Wo + bo      [8192,4096]  K=512    -> bf16
    Seg swo = { p_ctx, p_wot, bo, p_ch, 0, 0, 0,
                QROWS, Adim, Hdim, 1, 1.f, 32, 64 };
    gemm_one<<<dim3(32, 64, 1), 128, SMEM_GEMM>>>(swo);

    // out
    final_kernel<<<QROWS, 256>>>(hidden, p_ch, ln_out_w, ln_out_b, gate, out);
}